// round 1
// baseline (speedup 1.0000x reference)
#include <cuda_runtime.h>
#include <cuda_bf16.h>
#include <math.h>

#define B_ 4
#define T_ 40
#define R_ 2000
#define A_ 36864
#define H_ 64
#define W_ 64
#define C_ 256
#define PP_ 7
#define NCLS_ 21
#define NPOS_ 64
#define NNEG_ 192
#define DH_ 1024
#define D_ (PP_*PP_*C_)   // 12544

// ---------------- scratch (static __device__, no allocation) ----------------
__device__ float g_fmt[B_*H_*W_*C_];          // NHWC feature map (16 MB)
__device__ float g_maxiou[B_*A_];
__device__ int   g_tidx[B_*A_];
__device__ float g_ioum[B_*R_];
__device__ int   g_ridx[B_*R_];
__device__ int   g_pos[128];
__device__ int   g_neg[252];
__device__ int   g_posr[NPOS_];
__device__ int   g_negr[NNEG_];
__device__ float g_feat[256*D_];              // 12.8 MB
__device__ float g_partial[4][256*DH_];       // split-K partials (4 MB)
__device__ float g_hmid[256*DH_];
__device__ float g_rreg[256*4];
__device__ float g_rcls[256*NCLS_];

// ---------------- init selection buffers (nonzero pads with 0) ----------------
__global__ void init_sel_kernel() {
    int tid = threadIdx.x;
    if (tid < 128)  g_pos[tid]  = 0;
    if (tid < 252)  g_neg[tid]  = 0;
    if (tid < NPOS_) g_posr[tid] = 0;
}

// ---------------- NCHW -> NHWC transpose ----------------
__global__ void transpose_kernel(const float* __restrict__ fm) {
    __shared__ float tile[32][33];
    int bh = blockIdx.z;
    int b = bh / H_, y = bh % H_;
    int x0 = blockIdx.x * 32, c0 = blockIdx.y * 32;
    int tx = threadIdx.x, ty = threadIdx.y;
    tile[ty][tx] = fm[((b*C_ + (c0+ty))*H_ + y)*W_ + (x0+tx)];
    __syncthreads();
    g_fmt[((b*H_ + y)*W_ + (x0+ty))*C_ + (c0+tx)] = tile[tx][ty];
}

// ---------------- RPN IoU: per (b, anchor) max/argmax over T boxes ----------------
__global__ void rpn_iou_kernel(const float* __restrict__ bboxes,
                               const float* __restrict__ anchors) {
    __shared__ float sb[T_*4];
    int b = blockIdx.y;
    int tid = threadIdx.x;
    if (tid < T_*4) sb[tid] = bboxes[b*T_*4 + tid];
    __syncthreads();
    int a = blockIdx.x * blockDim.x + tid;
    if (a >= A_) return;
    float at = anchors[a*4+0], al = anchors[a*4+1];
    float ab = anchors[a*4+2], ar = anchors[a*4+3];
    float area2 = (ab-at)*(ar-al);
    float best = -1.0f; int bi = 0;
    #pragma unroll 4
    for (int t = 0; t < T_; t++) {
        float bt = sb[t*4+0], bl = sb[t*4+1], bb = sb[t*4+2], br = sb[t*4+3];
        float it = fmaxf(bt,at), il = fmaxf(bl,al);
        float ib = fminf(bb,ab), ir = fminf(br,ar);
        float inter = fmaxf(ib-it,0.f)*fmaxf(ir-il,0.f);
        float a1 = (bb-bt)*(br-bl);
        float iou = inter / (a1 + area2 - inter);
        if (iou > best) { best = iou; bi = t; }
    }
    g_maxiou[b*A_+a] = best;
    g_tidx[b*A_+a] = bi;
}

// ---------------- RCNN IoU: per (b, roi) max/argmax over T boxes ----------------
__global__ void rcnn_iou_kernel(const float* __restrict__ nms_reg,
                                const float* __restrict__ bboxes) {
    __shared__ float sb[T_*4];
    int b = blockIdx.y;
    int tid = threadIdx.x;
    if (tid < T_*4) sb[tid] = bboxes[b*T_*4 + tid];
    __syncthreads();
    int r = blockIdx.x * blockDim.x + tid;
    if (r >= R_) return;
    float nt = nms_reg[(b*R_+r)*4+0], nl = nms_reg[(b*R_+r)*4+1];
    float nb = nms_reg[(b*R_+r)*4+2], nr = nms_reg[(b*R_+r)*4+3];
    float area1 = (nb-nt)*(nr-nl);
    float best = -1.0f; int bi = 0;
    #pragma unroll 4
    for (int t = 0; t < T_; t++) {
        float bt = sb[t*4+0], bl = sb[t*4+1], bb = sb[t*4+2], br = sb[t*4+3];
        float it = fmaxf(bt,nt), il = fmaxf(bl,nl);
        float ib = fminf(bb,nb), ir = fminf(br,nr);
        float inter = fmaxf(ib-it,0.f)*fmaxf(ir-il,0.f);
        float a2 = (bb-bt)*(br-bl);
        float iou = inter / (area1 + a2 - inter);
        if (iou > best) { best = iou; bi = t; }
    }
    g_ioum[b*R_+r] = best;
    g_ridx[b*R_+r] = bi;
}

// ---------------- ordered first-K compaction (jnp.nonzero(size=K)) ----------------
// which==0: scan g_maxiou (n=B*A), pos cap 128 -> g_pos, neg cap 252 -> g_neg
// which==1: scan g_ioum   (n=B*R), pos cap 64  -> g_posr
__global__ void collect_kernel(int which) {
    const float* vals = (which == 0) ? g_maxiou : g_ioum;
    int n    = (which == 0) ? B_*A_ : B_*R_;
    int capP = (which == 0) ? 128 : NPOS_;
    int* outP = (which == 0) ? g_pos : g_posr;
    int capN = (which == 0) ? 252 : 0;
    int* outN = (which == 0) ? g_neg : nullptr;

    __shared__ int sCntP[32], sCntN[32], sOffP[32], sOffN[32];
    __shared__ int sTotP, sTotN;
    int tid = threadIdx.x, lane = tid & 31, wid = tid >> 5;
    int basePos = 0, baseNeg = 0;

    for (int start = 0; start < n; start += blockDim.x) {
        int i = start + tid;
        bool inr = (i < n);
        float v = inr ? vals[i] : 0.f;
        bool fp = inr && (v > 0.5f);
        bool fn = inr && !(v > 0.5f);
        unsigned mp = __ballot_sync(0xffffffffu, fp);
        unsigned mn = __ballot_sync(0xffffffffu, fn);
        if (lane == 0) { sCntP[wid] = __popc(mp); sCntN[wid] = __popc(mn); }
        __syncthreads();
        if (wid == 0) {
            int cp = sCntP[lane], cn = sCntN[lane];
            int sp = cp, sn = cn;
            #pragma unroll
            for (int d = 1; d < 32; d <<= 1) {
                int tp = __shfl_up_sync(0xffffffffu, sp, d);
                int tn = __shfl_up_sync(0xffffffffu, sn, d);
                if (lane >= d) { sp += tp; sn += tn; }
            }
            sOffP[lane] = sp - cp; sOffN[lane] = sn - cn;
            if (lane == 31) { sTotP = sp; sTotN = sn; }
        }
        __syncthreads();
        if (fp) {
            int p = basePos + sOffP[wid] + __popc(mp & ((1u << lane) - 1u));
            if (p < capP) outP[p] = i;
        }
        if (fn && outN) {
            int p = baseNeg + sOffN[wid] + __popc(mn & ((1u << lane) - 1u));
            if (p < capN) outN[p] = i;
        }
        basePos += sTotP; baseNeg += sTotN;
        __syncthreads();
        if (basePos >= capP && (!outN || baseNeg >= capN)) break;
    }
}

// ---------------- top-k(192) over negscore, lower-index tie break ----------------
__global__ void topk_kernel() {
    __shared__ float sv[B_*R_];
    __shared__ float rv[32];
    __shared__ int   ri[32];
    int tid = threadIdx.x;
    for (int j = tid; j < B_*R_; j += blockDim.x) {
        float v = g_ioum[j];
        sv[j] = (v <= 0.5f) ? v : -INFINITY;
    }
    __syncthreads();
    for (int round = 0; round < NNEG_; round++) {
        float bv = -INFINITY; int bi = 0x7fffffff;
        for (int j = tid; j < B_*R_; j += blockDim.x) {
            float v = sv[j];
            if (v > bv || (v == bv && j < bi)) { bv = v; bi = j; }
        }
        #pragma unroll
        for (int d = 16; d; d >>= 1) {
            float ov = __shfl_down_sync(0xffffffffu, bv, d);
            int   oi = __shfl_down_sync(0xffffffffu, bi, d);
            if (ov > bv || (ov == bv && oi < bi)) { bv = ov; bi = oi; }
        }
        if ((tid & 31) == 0) { rv[tid >> 5] = bv; ri[tid >> 5] = bi; }
        __syncthreads();
        if (tid < 32) {
            bv = rv[tid]; bi = ri[tid];
            #pragma unroll
            for (int d = 16; d; d >>= 1) {
                float ov = __shfl_down_sync(0xffffffffu, bv, d);
                int   oi = __shfl_down_sync(0xffffffffu, bi, d);
                if (ov > bv || (ov == bv && oi < bi)) { bv = ov; bi = oi; }
            }
            if (tid == 0) { g_negr[round] = bi; sv[bi] = NAN; }  // NaN never re-wins
        }
        __syncthreads();
    }
}

// ---------------- ROI pool (bilinear, 7x7, NHWC) ----------------
__global__ void roi_pool_kernel(const float* __restrict__ nms_reg) {
    int j = blockIdx.x;           // roi 0..255
    int c = threadIdx.x;          // channel 0..255
    int sel = (j < NPOS_) ? g_posr[j] : g_negr[j - NPOS_];
    int b = sel / R_;
    float t  = nms_reg[sel*4+0], l = nms_reg[sel*4+1];
    float bb = nms_reg[sel*4+2], r = nms_reg[sel*4+3];
    const float* fb = g_fmt + (size_t)b * H_ * W_ * C_;
    for (int p = 0; p < PP_*PP_; p++) {
        int py = p / PP_, px = p % PP_;
        float gy = (py + 0.5f) / (float)PP_;
        float gx = (px + 0.5f) / (float)PP_;
        float y = fminf(fmaxf(t + gy * (bb - t), 0.f), (float)(H_-1));
        float x = fminf(fmaxf(l + gx * (r  - l), 0.f), (float)(W_-1));
        int y0 = (int)floorf(y), x0 = (int)floorf(x);
        int y1 = min(y0 + 1, H_-1), x1 = min(x0 + 1, W_-1);
        float wy = y - (float)y0, wx = x - (float)x0;
        float v00 = fb[(y0*W_+x0)*C_ + c];
        float v01 = fb[(y0*W_+x1)*C_ + c];
        float v10 = fb[(y1*W_+x0)*C_ + c];
        float v11 = fb[(y1*W_+x1)*C_ + c];
        float v = v00*(1.f-wy)*(1.f-wx) + v01*(1.f-wy)*wx
                + v10*wy*(1.f-wx)       + v11*wy*wx;
        g_feat[(size_t)j*D_ + p*C_ + c] = v;
    }
}

// ---------------- GEMM: (256 x 12544) @ (12544 x 1024), split-K=4 ----------------
// BM=32, BN=64, BK=16; 256 threads; each thread 2x4. Deterministic partials.
__global__ void gemm_splitk_kernel(const float* __restrict__ W1) {
    __shared__ float As[16][33];
    __shared__ float Bs[16][64];
    int tid = threadIdx.x;
    int tx = tid % 16, ty = tid / 16;
    int n0 = blockIdx.x * 64;
    int m0 = blockIdx.y * 32;
    int kbase = blockIdx.z * (D_/4);       // 3136
    float acc[2][4] = {};
    for (int kt = 0; kt < D_/4; kt += 16) {
        int kg = kbase + kt;
        #pragma unroll
        for (int i = 0; i < 2; i++) {
            int idx = tid + i * 256;
            int kk = idx & 15, m = idx >> 4;
            As[kk][m] = g_feat[(size_t)(m0 + m) * D_ + kg + kk];
        }
        #pragma unroll
        for (int i = 0; i < 4; i++) {
            int idx = tid + i * 256;
            int n = idx & 63, kk = idx >> 6;
            Bs[kk][n] = W1[(size_t)(kg + kk) * DH_ + n0 + n];
        }
        __syncthreads();
        #pragma unroll
        for (int kk = 0; kk < 16; kk++) {
            float a0 = As[kk][ty*2+0], a1 = As[kk][ty*2+1];
            float b0 = Bs[kk][tx*4+0], b1v = Bs[kk][tx*4+1];
            float b2 = Bs[kk][tx*4+2], b3v = Bs[kk][tx*4+3];
            acc[0][0] += a0*b0;  acc[0][1] += a0*b1v;
            acc[0][2] += a0*b2;  acc[0][3] += a0*b3v;
            acc[1][0] += a1*b0;  acc[1][1] += a1*b1v;
            acc[1][2] += a1*b2;  acc[1][3] += a1*b3v;
        }
        __syncthreads();
    }
    float* outp = g_partial[blockIdx.z];
    #pragma unroll
    for (int i = 0; i < 2; i++)
        #pragma unroll
        for (int jj = 0; jj < 4; jj++)
            outp[(size_t)(m0 + ty*2 + i) * DH_ + n0 + tx*4 + jj] = acc[i][jj];
}

__global__ void reduce_bias_relu_kernel(const float* __restrict__ b1) {
    int i = blockIdx.x * blockDim.x + threadIdx.x;
    if (i < 256 * DH_) {
        float s = g_partial[0][i] + g_partial[1][i] + g_partial[2][i] + g_partial[3][i]
                + b1[i & (DH_-1)];
        g_hmid[i] = fmaxf(s, 0.f);
    }
}

// ---------------- heads: rreg (x4) and rcls (x21) ----------------
__global__ void heads_kernel(const float* __restrict__ Wr, const float* __restrict__ br,
                             const float* __restrict__ Wc, const float* __restrict__ bc) {
    __shared__ float h[DH_];
    int row = blockIdx.x;
    int tid = threadIdx.x;              // 128
    for (int k = tid; k < DH_; k += 128) h[k] = g_hmid[(size_t)row * DH_ + k];
    __syncthreads();
    int wid = tid >> 5, lane = tid & 31;
    for (int o = wid; o < 4 + NCLS_; o += 4) {
        float s = 0.f;
        if (o < 4) {
            for (int k = lane; k < DH_; k += 32) s += h[k] * Wr[k*4 + o];
        } else {
            int oc = o - 4;
            for (int k = lane; k < DH_; k += 32) s += h[k] * Wc[k*NCLS_ + oc];
        }
        #pragma unroll
        for (int d = 16; d; d >>= 1) s += __shfl_down_sync(0xffffffffu, s, d);
        if (lane == 0) {
            if (o < 4) g_rreg[row*4 + o] = s + br[o];
            else       g_rcls[row*NCLS_ + (o-4)] = s + bc[o-4];
        }
    }
}

// ---------------- finalize: all six scalars ----------------
__device__ float blockReduceSum512(float v, float* sbuf) {
    int tid = threadIdx.x;
    sbuf[tid] = v; __syncthreads();
    for (int s = 256; s > 0; s >>= 1) {
        if (tid < s) sbuf[tid] += sbuf[tid + s];
        __syncthreads();
    }
    float r = sbuf[0]; __syncthreads();
    return r;
}

__global__ void finalize_kernel(const float* __restrict__ nms_reg,
                                const float* __restrict__ bboxes,
                                const int*   __restrict__ classes,
                                const float* __restrict__ anchors,
                                const float* __restrict__ rpn_reg,
                                const float* __restrict__ rpn_cls,
                                float* __restrict__ out) {
    __shared__ float sbuf[512];
    int tid = threadIdx.x;

    // A: rpn_cls_loss (BCE with logits over 380)
    float a = 0.f;
    if (tid < 380) {
        int i = (tid < 128) ? g_pos[tid] : g_neg[tid - 128];
        float x = rpn_cls[i];
        float lbl = (tid < 128) ? 1.f : 0.f;
        a = fmaxf(x, 0.f) - x * lbl + log1pf(expf(-fabsf(x)));
    }
    float rpnCls = blockReduceSum512(a, sbuf) / 380.f;

    // B: rpn_reg_loss (smooth l1 over 128x4, mean then /4)
    float bsum = 0.f;
    {
        int jj = tid >> 2, c = tid & 3;   // 512 threads = 128*4 exactly
        int i = g_pos[jj];
        int b = i / A_;
        int aidx = i - b * A_;
        float pred = rpn_reg[i*4 + c];
        float tgt = bboxes[(b*T_ + g_tidx[i])*4 + c] - anchors[aidx*4 + c];
        float d = fabsf(pred - tgt);
        bsum = (d < 1.f) ? 0.5f*d*d : d - 0.5f;
    }
    float rpnReg = blockReduceSum512(bsum, sbuf) / 512.f / 4.f;

    // C: rcnn_cls_loss (NLL of log-softmax) + acc
    float csum = 0.f, accsum = 0.f;
    if (tid < 256) {
        int j = tid;
        int cls = 0;
        if (j < NPOS_) {
            int i = g_posr[j];
            int b = i / R_;
            cls = classes[b*T_ + g_ridx[i]];
        }
        const float* row = &g_rcls[j*NCLS_];
        float mx = row[0];
        #pragma unroll
        for (int c = 1; c < NCLS_; c++) mx = fmaxf(mx, row[c]);
        float se = 0.f;
        #pragma unroll
        for (int c = 0; c < NCLS_; c++) se += expf(row[c] - mx);
        float lse = mx + logf(se);
        csum = lse - row[cls];
        if (j < NPOS_) {
            int am = 0; float bv = row[0];
            #pragma unroll
            for (int c = 1; c < NCLS_; c++) if (row[c] > bv) { bv = row[c]; am = c; }
            accsum = (am == cls) ? 1.f : 0.f;
        }
    }
    float rcnnCls = blockReduceSum512(csum, sbuf) / 256.f;
    float acc     = blockReduceSum512(accsum, sbuf) / (float)NPOS_;

    // D: rcnn_reg_loss + offset (per-column means over 64, summed /4)
    float dsl = 0.f, dab = 0.f;
    if (tid < NPOS_*4) {
        int jj = tid >> 2, c = tid & 3;
        int i = g_posr[jj];
        int b = i / R_;
        float v = nms_reg[i*4 + c];
        float rounded = (c < 2) ? floorf(v * 16.f) / 16.f : ceilf(v * 16.f) / 16.f;
        float mb = bboxes[(b*T_ + g_ridx[i])*4 + c];
        float tgt = mb - rounded;
        float pr = g_rreg[jj*4 + c];
        float d = fabsf(pr - tgt);
        dsl = (d < 1.f) ? 0.5f*d*d : d - 0.5f;
        dab = d;
    }
    float rcnnReg = blockReduceSum512(dsl, sbuf) / (float)NPOS_ / 4.f;
    float offset  = blockReduceSum512(dab, sbuf) / (float)NPOS_ / 4.f;

    if (tid == 0) {
        out[0] = rpnCls;
        out[1] = rpnReg;
        out[2] = rcnnCls;
        out[3] = rcnnReg;
        out[4] = acc;
        out[5] = offset;
    }
}

// ---------------- launch ----------------
extern "C" void kernel_launch(void* const* d_in, const int* in_sizes, int n_in,
                              void* d_out, int out_size) {
    const float* nms_reg  = (const float*)d_in[0];
    // d_in[1] = nms_cls (unused by the reference)
    const float* fm       = (const float*)d_in[2];
    const float* bboxes   = (const float*)d_in[3];
    const int*   classes  = (const int*)  d_in[4];
    const float* anchors  = (const float*)d_in[5];
    const float* rpn_reg  = (const float*)d_in[6];
    const float* rpn_cls  = (const float*)d_in[7];
    const float* W1       = (const float*)d_in[8];
    const float* b1       = (const float*)d_in[9];
    const float* Wr       = (const float*)d_in[10];
    const float* br       = (const float*)d_in[11];
    const float* Wc       = (const float*)d_in[12];
    const float* bc       = (const float*)d_in[13];
    float* out = (float*)d_out;

    init_sel_kernel<<<1, 512>>>();
    transpose_kernel<<<dim3(W_/32, C_/32, B_*H_), dim3(32, 32)>>>(fm);
    rpn_iou_kernel<<<dim3(A_/256, B_), 256>>>(bboxes, anchors);
    rcnn_iou_kernel<<<dim3((R_+255)/256, B_), 256>>>(nms_reg, bboxes);
    collect_kernel<<<1, 1024>>>(0);     // rpn pos/neg
    collect_kernel<<<1, 1024>>>(1);     // rcnn posr
    topk_kernel<<<1, 1024>>>();         // rcnn negr
    roi_pool_kernel<<<256, 256>>>(nms_reg);
    gemm_splitk_kernel<<<dim3(DH_/64, 256/32, 4), 256>>>(W1);
    reduce_bias_relu_kernel<<<(256*DH_ + 255)/256, 256>>>(b1);
    heads_kernel<<<256, 128>>>(Wr, br, Wc, bc);
    finalize_kernel<<<1, 512>>>(nms_reg, bboxes, classes, anchors, rpn_reg, rpn_cls, out);
}

// round 3
// speedup vs baseline: 1.4785x; 1.4785x over previous
#include <cuda_runtime.h>
#include <cuda_bf16.h>
#include <math.h>
#include <stdint.h>

#define B_ 4
#define T_ 40
#define R_ 2000
#define A_ 36864
#define H_ 64
#define W_ 64
#define C_ 256
#define PP_ 7
#define NCLS_ 21
#define NPOS_ 64
#define NNEG_ 192
#define DH_ 1024
#define D_ (PP_*PP_*C_)   // 12544
#define KT_ 8             // split-K factor
#define KPC_ (D_/KT_)     // 1568 per CTA
#define BK_ 32
#define NIT_ (KPC_/BK_)   // 49

// smem tile layout: rows padded to 40 bf16 (80B) for conflict-free ldmatrix
#define TPAD_ 40
#define TILE_BYTES_ (128*TPAD_*2)       // 10240
#define STAGE_BYTES_ (4*TILE_BYTES_)    // 40960
#define SMEM_GEMM_ (2*STAGE_BYTES_)     // 81920

// ---------------- scratch ----------------
__device__ float g_fmt[B_*H_*W_*C_];
__device__ float g_maxiou[B_*A_];
__device__ int   g_tidx[B_*A_];
__device__ float g_ioum[B_*R_];
__device__ int   g_ridx[B_*R_];
__device__ int   g_pos[128];
__device__ int   g_neg[252];
__device__ int   g_posr[NPOS_];
__device__ int   g_negr[NNEG_];
__device__ __nv_bfloat16 g_Ahi[256*D_];
__device__ __nv_bfloat16 g_Alo[256*D_];
__device__ __nv_bfloat16 g_Bhi[DH_*D_];
__device__ __nv_bfloat16 g_Blo[DH_*D_];
__device__ float g_partial[KT_][256*DH_];
__device__ float g_hmid[256*DH_];
__device__ float g_rreg[256*4];
__device__ float g_rcls[256*NCLS_];

__device__ __forceinline__ uint32_t smem_u32(const void* p) {
    uint32_t a;
    asm("{ .reg .u64 t; cvta.to.shared.u64 t, %1; cvt.u32.u64 %0, t; }" : "=r"(a) : "l"(p));
    return a;
}

// ---------------- init selection buffers ----------------
__global__ void init_sel_kernel() {
    int tid = threadIdx.x;
    if (tid < 128)  g_pos[tid]  = 0;
    if (tid < 252)  g_neg[tid]  = 0;
    if (tid < NPOS_) g_posr[tid] = 0;
}

// ---------------- NCHW -> NHWC transpose ----------------
__global__ void transpose_kernel(const float* __restrict__ fm) {
    __shared__ float tile[32][33];
    int bh = blockIdx.z;
    int b = bh / H_, y = bh % H_;
    int x0 = blockIdx.x * 32, c0 = blockIdx.y * 32;
    int tx = threadIdx.x, ty = threadIdx.y;
    tile[ty][tx] = fm[((b*C_ + (c0+ty))*H_ + y)*W_ + (x0+tx)];
    __syncthreads();
    g_fmt[((b*H_ + y)*W_ + (x0+ty))*C_ + (c0+tx)] = tile[tx][ty];
}

// ---------------- W1 fp32 -> transposed bf16 hi/lo ----------------
__global__ void convertB_kernel(const float* __restrict__ W1) {
    __shared__ float tile[32][33];
    int k0 = blockIdx.x * 32, n0 = blockIdx.y * 32;
    int tx = threadIdx.x, ty = threadIdx.y;
    tile[ty][tx] = W1[(size_t)(k0+ty)*DH_ + n0+tx];
    __syncthreads();
    float v = tile[tx][ty];   // W1[k0+tx][n0+ty]
    __nv_bfloat16 h = __float2bfloat16(v);
    __nv_bfloat16 l = __float2bfloat16(v - __bfloat162float(h));
    size_t o = (size_t)(n0+ty)*D_ + k0+tx;
    g_Bhi[o] = h; g_Blo[o] = l;
}

// ---------------- RPN IoU ----------------
__global__ void rpn_iou_kernel(const float* __restrict__ bboxes,
                               const float* __restrict__ anchors) {
    __shared__ float sb[T_*4];
    int b = blockIdx.y;
    int tid = threadIdx.x;
    if (tid < T_*4) sb[tid] = bboxes[b*T_*4 + tid];
    __syncthreads();
    int a = blockIdx.x * blockDim.x + tid;
    if (a >= A_) return;
    float at = anchors[a*4+0], al = anchors[a*4+1];
    float ab = anchors[a*4+2], ar = anchors[a*4+3];
    float area2 = (ab-at)*(ar-al);
    float best = -1.0f; int bi = 0;
    #pragma unroll 4
    for (int t = 0; t < T_; t++) {
        float bt = sb[t*4+0], bl = sb[t*4+1], bb = sb[t*4+2], br = sb[t*4+3];
        float it = fmaxf(bt,at), il = fmaxf(bl,al);
        float ib = fminf(bb,ab), ir = fminf(br,ar);
        float inter = fmaxf(ib-it,0.f)*fmaxf(ir-il,0.f);
        float a1 = (bb-bt)*(br-bl);
        float iou = inter / (a1 + area2 - inter);
        if (iou > best) { best = iou; bi = t; }
    }
    g_maxiou[b*A_+a] = best;
    g_tidx[b*A_+a] = bi;
}

// ---------------- RCNN IoU ----------------
__global__ void rcnn_iou_kernel(const float* __restrict__ nms_reg,
                                const float* __restrict__ bboxes) {
    __shared__ float sb[T_*4];
    int b = blockIdx.y;
    int tid = threadIdx.x;
    if (tid < T_*4) sb[tid] = bboxes[b*T_*4 + tid];
    __syncthreads();
    int r = blockIdx.x * blockDim.x + tid;
    if (r >= R_) return;
    float nt = nms_reg[(b*R_+r)*4+0], nl = nms_reg[(b*R_+r)*4+1];
    float nb = nms_reg[(b*R_+r)*4+2], nr = nms_reg[(b*R_+r)*4+3];
    float area1 = (nb-nt)*(nr-nl);
    float best = -1.0f; int bi = 0;
    #pragma unroll 4
    for (int t = 0; t < T_; t++) {
        float bt = sb[t*4+0], bl = sb[t*4+1], bb = sb[t*4+2], br = sb[t*4+3];
        float it = fmaxf(bt,nt), il = fmaxf(bl,nl);
        float ib = fminf(bb,nb), ir = fminf(br,nr);
        float inter = fmaxf(ib-it,0.f)*fmaxf(ir-il,0.f);
        float a2 = (bb-bt)*(br-bl);
        float iou = inter / (area1 + a2 - inter);
        if (iou > best) { best = iou; bi = t; }
    }
    g_ioum[b*R_+r] = best;
    g_ridx[b*R_+r] = bi;
}

// ---------------- ordered first-K compaction, 8 elems/thread/iter ----------------
__global__ void collect_kernel(int which) {
    const float* vals = (which == 0) ? g_maxiou : g_ioum;
    int n    = (which == 0) ? B_*A_ : B_*R_;
    int capP = (which == 0) ? 128 : NPOS_;
    int* outP = (which == 0) ? g_pos : g_posr;
    int capN = (which == 0) ? 252 : 0;
    int* outN = (which == 0) ? g_neg : nullptr;

    __shared__ int sCntP[32], sCntN[32], sOffP[32], sOffN[32];
    __shared__ int sTotP, sTotN;
    int tid = threadIdx.x, lane = tid & 31, wid = tid >> 5;
    int basePos = 0, baseNeg = 0;

    for (int start = 0; start < n; start += 8192) {
        float v[8]; int idx_[8]; bool ok[8];
        #pragma unroll
        for (int j = 0; j < 8; j++) {
            int i = start + j*1024 + tid;
            idx_[j] = i; ok[j] = (i < n);
            v[j] = ok[j] ? vals[i] : 0.f;
        }
        #pragma unroll
        for (int j = 0; j < 8; j++) {
            bool fp = ok[j] && (v[j] > 0.5f);
            bool fn = ok[j] && !(v[j] > 0.5f);
            unsigned mp = __ballot_sync(0xffffffffu, fp);
            unsigned mn = __ballot_sync(0xffffffffu, fn);
            if (lane == 0) { sCntP[wid] = __popc(mp); sCntN[wid] = __popc(mn); }
            __syncthreads();
            if (wid == 0) {
                int cp = sCntP[lane], cn = sCntN[lane];
                int sp = cp, sn = cn;
                #pragma unroll
                for (int d = 1; d < 32; d <<= 1) {
                    int tp = __shfl_up_sync(0xffffffffu, sp, d);
                    int tn = __shfl_up_sync(0xffffffffu, sn, d);
                    if (lane >= d) { sp += tp; sn += tn; }
                }
                sOffP[lane] = sp - cp; sOffN[lane] = sn - cn;
                if (lane == 31) { sTotP = sp; sTotN = sn; }
            }
            __syncthreads();
            if (fp) {
                int p = basePos + sOffP[wid] + __popc(mp & ((1u << lane) - 1u));
                if (p < capP) outP[p] = idx_[j];
            }
            if (fn && outN) {
                int p = baseNeg + sOffN[wid] + __popc(mn & ((1u << lane) - 1u));
                if (p < capN) outN[p] = idx_[j];
            }
            basePos += sTotP; baseNeg += sTotN;
            __syncthreads();
        }
        if (basePos >= capP && (!outN || baseNeg >= capN)) break;
    }
}

// ---------------- top-k(192): cached per-warp maxima ----------------
__global__ void topk_kernel() {
    __shared__ float sv[B_*R_];
    __shared__ float wv[8];
    __shared__ int   wi_[8];
    __shared__ int   winner;
    int tid = threadIdx.x;              // 256 threads, 8 warps
    int lane = tid & 31, wid = tid >> 5;
    for (int j = tid; j < B_*R_; j += 256) {
        float v = g_ioum[j];
        sv[j] = (v <= 0.5f) ? v : -INFINITY;
    }
    __syncthreads();
    {
        int base = wid * 1000;
        float bv = -INFINITY; int bi = 0x7fffffff;
        for (int j = base + lane; j < base + 1000; j += 32) {
            float x = sv[j];
            if (x > bv || (x == bv && j < bi)) { bv = x; bi = j; }
        }
        #pragma unroll
        for (int d = 16; d; d >>= 1) {
            float ov = __shfl_down_sync(0xffffffffu, bv, d);
            int   oi = __shfl_down_sync(0xffffffffu, bi, d);
            if (ov > bv || (ov == bv && oi < bi)) { bv = ov; bi = oi; }
        }
        if (lane == 0) { wv[wid] = bv; wi_[wid] = bi; }
    }
    __syncthreads();
    for (int r = 0; r < NNEG_; r++) {
        if (tid < 8) {
            float bv = wv[tid]; int bi = wi_[tid];
            #pragma unroll
            for (int d = 4; d; d >>= 1) {
                float ov = __shfl_down_sync(0xffu, bv, d);
                int   oi = __shfl_down_sync(0xffu, bi, d);
                if (ov > bv || (ov == bv && oi < bi)) { bv = ov; bi = oi; }
            }
            if (tid == 0) {
                g_negr[r] = bi;
                sv[bi] = NAN;           // NaN never re-wins
                winner = bi / 1000;
            }
        }
        __syncthreads();
        int bw = winner;
        if (wid == bw) {
            int base = bw * 1000;
            float bv = -INFINITY; int bi = 0x7fffffff;
            for (int j = base + lane; j < base + 1000; j += 32) {
                float x = sv[j];
                if (x > bv || (x == bv && j < bi)) { bv = x; bi = j; }
            }
            #pragma unroll
            for (int d = 16; d; d >>= 1) {
                float ov = __shfl_down_sync(0xffffffffu, bv, d);
                int   oi = __shfl_down_sync(0xffffffffu, bi, d);
                if (ov > bv || (ov == bv && oi < bi)) { bv = ov; bi = oi; }
            }
            if (lane == 0) { wv[bw] = bv; wi_[bw] = bi; }
        }
        __syncthreads();
    }
}

// ---------------- ROI pool -> bf16 hi/lo feature matrix ----------------
__global__ void roi_pool_kernel(const float* __restrict__ nms_reg) {
    int j = blockIdx.x;
    int c = threadIdx.x;
    int sel = (j < NPOS_) ? g_posr[j] : g_negr[j - NPOS_];
    int b = sel / R_;
    float t  = nms_reg[sel*4+0], l = nms_reg[sel*4+1];
    float bb = nms_reg[sel*4+2], r = nms_reg[sel*4+3];
    const float* fb = g_fmt + (size_t)b * H_ * W_ * C_;
    for (int p = 0; p < PP_*PP_; p++) {
        int py = p / PP_, px = p % PP_;
        float gy = (py + 0.5f) / (float)PP_;
        float gx = (px + 0.5f) / (float)PP_;
        float y = fminf(fmaxf(t + gy * (bb - t), 0.f), (float)(H_-1));
        float x = fminf(fmaxf(l + gx * (r  - l), 0.f), (float)(W_-1));
        int y0 = (int)floorf(y), x0 = (int)floorf(x);
        int y1 = min(y0 + 1, H_-1), x1 = min(x0 + 1, W_-1);
        float wy = y - (float)y0, wx = x - (float)x0;
        float v00 = fb[(y0*W_+x0)*C_ + c];
        float v01 = fb[(y0*W_+x1)*C_ + c];
        float v10 = fb[(y1*W_+x0)*C_ + c];
        float v11 = fb[(y1*W_+x1)*C_ + c];
        float v = v00*(1.f-wy)*(1.f-wx) + v01*(1.f-wy)*wx
                + v10*wy*(1.f-wx)       + v11*wy*wx;
        __nv_bfloat16 h = __float2bfloat16(v);
        int o = j*D_ + p*C_ + c;
        g_Ahi[o] = h;
        g_Alo[o] = __float2bfloat16(v - __bfloat162float(h));
    }
}

// ---------------- mma.sync GEMM, bf16 hi/lo split, split-K ----------------
// grid (8 Ntiles, 2 Mtiles, 8 Ktiles), 256 threads (8 warps, 2x4)
__device__ __forceinline__ void ldsm_x4(uint32_t* r, uint32_t addr) {
    asm volatile("ldmatrix.sync.aligned.m8n8.x4.shared.b16 {%0,%1,%2,%3}, [%4];"
        : "=r"(r[0]), "=r"(r[1]), "=r"(r[2]), "=r"(r[3]) : "r"(addr));
}
__device__ __forceinline__ void ldsm_x2(uint32_t* r, uint32_t addr) {
    asm volatile("ldmatrix.sync.aligned.m8n8.x2.shared.b16 {%0,%1}, [%2];"
        : "=r"(r[0]), "=r"(r[1]) : "r"(addr));
}
__device__ __forceinline__ void mma16816(float* d, const uint32_t* a, const uint32_t* b) {
    asm volatile("mma.sync.aligned.m16n8k16.row.col.f32.bf16.bf16.f32 "
        "{%0,%1,%2,%3}, {%4,%5,%6,%7}, {%8,%9}, {%0,%1,%2,%3};"
        : "+f"(d[0]), "+f"(d[1]), "+f"(d[2]), "+f"(d[3])
        : "r"(a[0]), "r"(a[1]), "r"(a[2]), "r"(a[3]), "r"(b[0]), "r"(b[1]));
}
__device__ __forceinline__ void cp16(uint32_t saddr, const void* gaddr) {
    asm volatile("cp.async.cg.shared.global [%0], [%1], 16;" :: "r"(saddr), "l"(gaddr));
}

__global__ void __launch_bounds__(256, 1) gemm_mma_kernel() {
    extern __shared__ char smem[];
    uint32_t sb = smem_u32(smem);
    int tid = threadIdx.x, wid = tid >> 5, lane = tid & 31;
    int n0 = blockIdx.x * 128;
    int m0 = blockIdx.y * 128;
    int kt = blockIdx.z;
    int kbase = kt * KPC_;
    int wm = wid >> 2, wn = wid & 3;     // warp tile: (wm*64, wn*32)

    const uint4* bAhi = (const uint4*)g_Ahi + (size_t)m0 * (D_/8);
    const uint4* bAlo = (const uint4*)g_Alo + (size_t)m0 * (D_/8);
    const uint4* bBhi = (const uint4*)g_Bhi + (size_t)n0 * (D_/8);
    const uint4* bBlo = (const uint4*)g_Blo + (size_t)n0 * (D_/8);

    // per-thread load slots: 2 chunks of 16B per tile
    int c0r = (tid*2) >> 2,  c0c = (tid*2) & 3;      // chunk tid*2
    int c1r = (tid*2+1) >> 2, c1c = (tid*2+1) & 3;   // chunk tid*2+1

    auto load_stage = [&](int stg, int it) {
        uint32_t sbase = sb + stg * STAGE_BYTES_;
        int kq = (kbase + it*BK_) >> 3;
        const uint4* srcs[4] = { bAhi, bAlo, bBhi, bBlo };
        #pragma unroll
        for (int tl = 0; tl < 4; tl++) {
            uint32_t tb = sbase + tl * TILE_BYTES_;
            cp16(tb + c0r*(TPAD_*2) + c0c*16, srcs[tl] + (size_t)c0r*(D_/8) + kq + c0c);
            cp16(tb + c1r*(TPAD_*2) + c1c*16, srcs[tl] + (size_t)c1r*(D_/8) + kq + c1c);
        }
        asm volatile("cp.async.commit_group;");
    };

    float acc[4][4][4];
    #pragma unroll
    for (int i = 0; i < 4; i++)
        #pragma unroll
        for (int j = 0; j < 4; j++)
            #pragma unroll
            for (int q = 0; q < 4; q++) acc[i][j][q] = 0.f;

    load_stage(0, 0);

    for (int it = 0; it < NIT_; it++) {
        if (it + 1 < NIT_) load_stage((it+1) & 1, it+1);
        if (it + 1 < NIT_) asm volatile("cp.async.wait_group 1;");
        else               asm volatile("cp.async.wait_group 0;");
        __syncthreads();

        uint32_t sbase = sb + (it & 1) * STAGE_BYTES_;
        uint32_t aHiB = sbase;
        uint32_t aLoB = sbase + TILE_BYTES_;
        uint32_t bHiB = sbase + 2*TILE_BYTES_;
        uint32_t bLoB = sbase + 3*TILE_BYTES_;

        #pragma unroll
        for (int ks = 0; ks < 2; ks++) {
            int acol = ks*16 + ((lane >> 4) & 1) * 8;   // A: k offset
            int bcol = ks*16 + ((lane >> 3) & 1) * 8;   // B: k offset
            uint32_t ahi[4][4], alo[4][4], bhi[4][2], blo[4][2];
            #pragma unroll
            for (int mt = 0; mt < 4; mt++) {
                int arow = wm*64 + mt*16 + (lane & 15);
                uint32_t off = arow*(TPAD_*2) + acol*2;
                ldsm_x4(ahi[mt], aHiB + off);
                ldsm_x4(alo[mt], aLoB + off);
            }
            #pragma unroll
            for (int nt = 0; nt < 4; nt++) {
                int brow = wn*32 + nt*8 + (lane & 7);
                uint32_t off = brow*(TPAD_*2) + bcol*2;
                ldsm_x2(bhi[nt], bHiB + off);
                ldsm_x2(blo[nt], bLoB + off);
            }
            #pragma unroll
            for (int mt = 0; mt < 4; mt++)
                #pragma unroll
                for (int nt = 0; nt < 4; nt++) {
                    mma16816(acc[mt][nt], ahi[mt], bhi[nt]);
                    mma16816(acc[mt][nt], ahi[mt], blo[nt]);
                    mma16816(acc[mt][nt], alo[mt], bhi[nt]);
                }
        }
        __syncthreads();
    }

    // epilogue: write split-K partials
    float* outp = g_partial[kt];
    int g = lane >> 2, qc = (lane & 3) * 2;
    #pragma unroll
    for (int mt = 0; mt < 4; mt++) {
        #pragma unroll
        for (int nt = 0; nt < 4; nt++) {
            int row = m0 + wm*64 + mt*16 + g;
            int col = n0 + wn*32 + nt*8 + qc;
            *(float2*)&outp[(size_t)row*DH_ + col]     = make_float2(acc[mt][nt][0], acc[mt][nt][1]);
            *(float2*)&outp[(size_t)(row+8)*DH_ + col] = make_float2(acc[mt][nt][2], acc[mt][nt][3]);
        }
    }
}

// ---------------- reduce partials + bias + relu ----------------
__global__ void reduce_bias_relu_kernel(const float* __restrict__ b1) {
    int i4 = blockIdx.x * 256 + threadIdx.x;   // 65536 float4s
    const float4* b4 = (const float4*)b1;
    float4 bias = b4[i4 & 255];
    float4 s = bias;
    #pragma unroll
    for (int k = 0; k < KT_; k++) {
        float4 p = ((const float4*)g_partial[k])[i4];
        s.x += p.x; s.y += p.y; s.z += p.z; s.w += p.w;
    }
    float4 o;
    o.x = fmaxf(s.x, 0.f); o.y = fmaxf(s.y, 0.f);
    o.z = fmaxf(s.z, 0.f); o.w = fmaxf(s.w, 0.f);
    ((float4*)g_hmid)[i4] = o;
}

// ---------------- heads ----------------
__global__ void heads_kernel(const float* __restrict__ Wr, const float* __restrict__ br,
                             const float* __restrict__ Wc, const float* __restrict__ bc) {
    __shared__ float h[DH_];
    int row = blockIdx.x;
    int tid = threadIdx.x;
    for (int k = tid; k < DH_; k += 128) h[k] = g_hmid[(size_t)row * DH_ + k];
    __syncthreads();
    int wid = tid >> 5, lane = tid & 31;
    for (int o = wid; o < 4 + NCLS_; o += 4) {
        float s = 0.f;
        if (o < 4) {
            for (int k = lane; k < DH_; k += 32) s += h[k] * Wr[k*4 + o];
        } else {
            int oc = o - 4;
            for (int k = lane; k < DH_; k += 32) s += h[k] * Wc[k*NCLS_ + oc];
        }
        #pragma unroll
        for (int d = 16; d; d >>= 1) s += __shfl_down_sync(0xffffffffu, s, d);
        if (lane == 0) {
            if (o < 4) g_rreg[row*4 + o] = s + br[o];
            else       g_rcls[row*NCLS_ + (o-4)] = s + bc[o-4];
        }
    }
}

// ---------------- finalize ----------------
__device__ float blockReduceSum512(float v, float* sbuf) {
    int tid = threadIdx.x;
    sbuf[tid] = v; __syncthreads();
    for (int s = 256; s > 0; s >>= 1) {
        if (tid < s) sbuf[tid] += sbuf[tid + s];
        __syncthreads();
    }
    float r = sbuf[0]; __syncthreads();
    return r;
}

__global__ void finalize_kernel(const float* __restrict__ nms_reg,
                                const float* __restrict__ bboxes,
                                const int*   __restrict__ classes,
                                const float* __restrict__ anchors,
                                const float* __restrict__ rpn_reg,
                                const float* __restrict__ rpn_cls,
                                float* __restrict__ out) {
    __shared__ float sbuf[512];
    int tid = threadIdx.x;

    float a = 0.f;
    if (tid < 380) {
        int i = (tid < 128) ? g_pos[tid] : g_neg[tid - 128];
        float x = rpn_cls[i];
        float lbl = (tid < 128) ? 1.f : 0.f;
        a = fmaxf(x, 0.f) - x * lbl + log1pf(expf(-fabsf(x)));
    }
    float rpnCls = blockReduceSum512(a, sbuf) / 380.f;

    float bsum = 0.f;
    {
        int jj = tid >> 2, c = tid & 3;
        int i = g_pos[jj];
        int b = i / A_;
        int aidx = i - b * A_;
        float pred = rpn_reg[i*4 + c];
        float tgt = bboxes[(b*T_ + g_tidx[i])*4 + c] - anchors[aidx*4 + c];
        float d = fabsf(pred - tgt);
        bsum = (d < 1.f) ? 0.5f*d*d : d - 0.5f;
    }
    float rpnReg = blockReduceSum512(bsum, sbuf) / 512.f / 4.f;

    float csum = 0.f, accsum = 0.f;
    if (tid < 256) {
        int j = tid;
        int cls = 0;
        if (j < NPOS_) {
            int i = g_posr[j];
            int b = i / R_;
            cls = classes[b*T_ + g_ridx[i]];
        }
        const float* row = &g_rcls[j*NCLS_];
        float mx = row[0];
        #pragma unroll
        for (int c = 1; c < NCLS_; c++) mx = fmaxf(mx, row[c]);
        float se = 0.f;
        #pragma unroll
        for (int c = 0; c < NCLS_; c++) se += expf(row[c] - mx);
        float lse = mx + logf(se);
        csum = lse - row[cls];
        if (j < NPOS_) {
            int am = 0; float bv = row[0];
            #pragma unroll
            for (int c = 1; c < NCLS_; c++) if (row[c] > bv) { bv = row[c]; am = c; }
            accsum = (am == cls) ? 1.f : 0.f;
        }
    }
    float rcnnCls = blockReduceSum512(csum, sbuf) / 256.f;
    float acc     = blockReduceSum512(accsum, sbuf) / (float)NPOS_;

    float dsl = 0.f, dab = 0.f;
    if (tid < NPOS_*4) {
        int jj = tid >> 2, c = tid & 3;
        int i = g_posr[jj];
        int b = i / R_;
        float v = nms_reg[i*4 + c];
        float rounded = (c < 2) ? floorf(v * 16.f) / 16.f : ceilf(v * 16.f) / 16.f;
        float mb = bboxes[(b*T_ + g_ridx[i])*4 + c];
        float tgt = mb - rounded;
        float pr = g_rreg[jj*4 + c];
        float d = fabsf(pr - tgt);
        dsl = (d < 1.f) ? 0.5f*d*d : d - 0.5f;
        dab = d;
    }
    float rcnnReg = blockReduceSum512(dsl, sbuf) / (float)NPOS_ / 4.f;
    float offset  = blockReduceSum512(dab, sbuf) / (float)NPOS_ / 4.f;

    if (tid == 0) {
        out[0] = rpnCls;
        out[1] = rpnReg;
        out[2] = rcnnCls;
        out[3] = rcnnReg;
        out[4] = acc;
        out[5] = offset;
    }
}

// ---------------- launch ----------------
extern "C" void kernel_launch(void* const* d_in, const int* in_sizes, int n_in,
                              void* d_out, int out_size) {
    const float* nms_reg  = (const float*)d_in[0];
    const float* fm       = (const float*)d_in[2];
    const float* bboxes   = (const float*)d_in[3];
    const int*   classes  = (const int*)  d_in[4];
    const float* anchors  = (const float*)d_in[5];
    const float* rpn_reg  = (const float*)d_in[6];
    const float* rpn_cls  = (const float*)d_in[7];
    const float* W1       = (const float*)d_in[8];
    const float* b1       = (const float*)d_in[9];
    const float* Wr       = (const float*)d_in[10];
    const float* br       = (const float*)d_in[11];
    const float* Wc       = (const float*)d_in[12];
    const float* bc       = (const float*)d_in[13];
    float* out = (float*)d_out;

    cudaFuncSetAttribute(gemm_mma_kernel, cudaFuncAttributeMaxDynamicSharedMemorySize, SMEM_GEMM_);

    init_sel_kernel<<<1, 512>>>();
    convertB_kernel<<<dim3(D_/32, DH_/32), dim3(32, 32)>>>(W1);
    transpose_kernel<<<dim3(W_/32, C_/32, B_*H_), dim3(32, 32)>>>(fm);
    rpn_iou_kernel<<<dim3(A_/256, B_), 256>>>(bboxes, anchors);
    rcnn_iou_kernel<<<dim3((R_+255)/256, B_), 256>>>(nms_reg, bboxes);
    collect_kernel<<<1, 1024>>>(0);
    collect_kernel<<<1, 1024>>>(1);
    topk_kernel<<<1, 256>>>();
    roi_pool_kernel<<<256, 256>>>(nms_reg);
    gemm_mma_kernel<<<dim3(8, 2, KT_), 256, SMEM_GEMM_>>>();
    reduce_bias_relu_kernel<<<256, 256>>>(b1);
    heads_kernel<<<256, 128>>>(Wr, br, Wc, bc);
    finalize_kernel<<<1, 512>>>(nms_reg, bboxes, classes, anchors, rpn_reg, rpn_cls, out);
}

// round 4
// speedup vs baseline: 2.9210x; 1.9757x over previous
#include <cuda_runtime.h>
#include <cuda_bf16.h>
#include <math.h>
#include <stdint.h>

#define B_ 4
#define T_ 40
#define R_ 2000
#define A_ 36864
#define H_ 64
#define W_ 64
#define C_ 256
#define PP_ 7
#define NCLS_ 21
#define NPOS_ 64
#define NNEG_ 192
#define DH_ 1024
#define D_ (PP_*PP_*C_)   // 12544
#define KT_ 8             // split-K factor
#define KPC_ (D_/KT_)     // 1568 per CTA
#define BK_ 32
#define NIT_ (KPC_/BK_)   // 49

// GEMM tiles: BM=128, BN=64. smem rows padded to 40 bf16 (80B): conflict-free ldmatrix
#define TPAD_ 40
#define ATILE_ (128*TPAD_*2)            // 10240
#define BTILE_ (64*TPAD_*2)             // 5120
#define STAGE_ (2*ATILE_ + 2*BTILE_)    // 30720
#define NSTG_ 3
#define SMEM_GEMM_ (NSTG_*STAGE_)       // 92160

// ---------------- scratch ----------------
__device__ float g_fmt[B_*H_*W_*C_];
__device__ float g_maxiou[B_*A_];
__device__ int   g_tidx[B_*A_];
__device__ float g_ioum[B_*R_];
__device__ int   g_ridx[B_*R_];
__device__ int   g_pos[128];
__device__ int   g_neg[252];
__device__ int   g_posr[NPOS_];
__device__ int   g_negr[NNEG_];
__device__ int   g_cntP[18], g_cntN[18], g_offP[18], g_offN[18];
__device__ __nv_bfloat16 g_Ahi[256*D_];
__device__ __nv_bfloat16 g_Alo[256*D_];
__device__ __nv_bfloat16 g_Bhi[DH_*D_];
__device__ __nv_bfloat16 g_Blo[DH_*D_];
__device__ float g_partial[KT_][256*DH_];
__device__ float g_hmid[256*DH_];
__device__ float g_rreg[256*4];
__device__ float g_rcls[256*NCLS_];

__device__ __forceinline__ uint32_t smem_u32(const void* p) {
    uint32_t a;
    asm("{ .reg .u64 t; cvta.to.shared.u64 t, %1; cvt.u32.u64 %0, t; }" : "=r"(a) : "l"(p));
    return a;
}
__device__ __forceinline__ unsigned fkey(float f) {
    unsigned u = __float_as_uint(f);
    return (u & 0x80000000u) ? ~u : (u | 0x80000000u);
}

// ---------------- init selection buffers (nonzero pads with 0) ----------------
__global__ void init_sel_kernel() {
    int tid = threadIdx.x;
    if (tid < 128)  g_pos[tid]  = 0;
    if (tid < 252)  g_neg[tid]  = 0;
    if (tid < NPOS_) g_posr[tid] = 0;
}

// ---------------- fused prep: convertB | transpose | rpn_iou | rcnn_iou ----------------
#define PB_CONV  12544                  // (D/32)*(DH/32)
#define PB_TRANS 4096                   // 2*8*256
#define PB_RPN   576                    // 144*4
#define PB_RCNN  32                     // 8*4
#define PB_TOTAL (PB_CONV + PB_TRANS + PB_RPN + PB_RCNN)

__global__ void prep_kernel(const float* __restrict__ W1,
                            const float* __restrict__ fm,
                            const float* __restrict__ bboxes,
                            const float* __restrict__ anchors,
                            const float* __restrict__ nms_reg) {
    __shared__ float tile[32][33];
    int blk = blockIdx.x;
    int tid = threadIdx.x;          // 256
    if (blk < PB_CONV) {
        // W1 fp32 -> transposed bf16 hi/lo. Tile (32k x 32n)
        int k0 = (blk % (D_/32)) * 32, n0 = (blk / (D_/32)) * 32;
        #pragma unroll
        for (int i = 0; i < 4; i++) {
            int idx = tid + i*256;
            int row = idx >> 5, col = idx & 31;
            tile[row][col] = W1[(size_t)(k0+row)*DH_ + n0+col];
        }
        __syncthreads();
        #pragma unroll
        for (int i = 0; i < 4; i++) {
            int idx = tid + i*256;
            int nr = idx >> 5, kc = idx & 31;   // write along k contiguously
            float v = tile[kc][nr];             // W1[k0+kc][n0+nr]
            __nv_bfloat16 h = __float2bfloat16(v);
            size_t o = (size_t)(n0+nr)*D_ + k0+kc;
            g_Bhi[o] = h;
            g_Blo[o] = __float2bfloat16(v - __bfloat162float(h));
        }
        return;
    }
    blk -= PB_CONV;
    if (blk < PB_TRANS) {
        // NCHW -> NHWC
        int bh = blk >> 4;                      // 0..255  (b*H + y)
        int sub = blk & 15;                     // x-tile (2) * c-tile (8)
        int x0 = (sub & 1) * 32, c0 = (sub >> 1) * 32;
        int b = bh >> 6, y = bh & 63;
        int tx = tid & 31, ty = tid >> 5;       // 32 x 8
        #pragma unroll
        for (int i = 0; i < 4; i++) {
            int c = c0 + ty + i*8;
            tile[ty + i*8][tx] = fm[((b*C_ + c)*H_ + y)*W_ + x0 + tx];
        }
        __syncthreads();
        #pragma unroll
        for (int i = 0; i < 4; i++) {
            int xr = ty + i*8;
            g_fmt[((b*H_ + y)*W_ + x0+xr)*C_ + c0+tx] = tile[tx][xr];
        }
        return;
    }
    blk -= PB_TRANS;
    if (blk < PB_RPN) {
        int b = blk / 144, bx = blk % 144;
        float* sb = &tile[0][0];
        if (tid < T_*4) sb[tid] = bboxes[b*T_*4 + tid];
        __syncthreads();
        int a = bx*256 + tid;
        float4 an = ((const float4*)anchors)[a];
        float area2 = (an.z-an.x)*(an.w-an.y);
        float best = -1.0f; int bi = 0;
        #pragma unroll 4
        for (int t = 0; t < T_; t++) {
            float bt = sb[t*4+0], bl = sb[t*4+1], bb = sb[t*4+2], br = sb[t*4+3];
            float inter = fmaxf(fminf(bb,an.z)-fmaxf(bt,an.x),0.f)
                        * fmaxf(fminf(br,an.w)-fmaxf(bl,an.y),0.f);
            float a1 = (bb-bt)*(br-bl);
            float iou = inter / (a1 + area2 - inter);
            if (iou > best) { best = iou; bi = t; }
        }
        g_maxiou[b*A_+a] = best;
        g_tidx[b*A_+a] = bi;
        return;
    }
    blk -= PB_RPN;
    {
        int b = blk >> 3, rx = blk & 7;
        float* sb = &tile[0][0];
        if (tid < T_*4) sb[tid] = bboxes[b*T_*4 + tid];
        __syncthreads();
        int r = rx*256 + tid;
        if (r >= R_) return;
        float4 nr4 = ((const float4*)nms_reg)[b*R_+r];
        float area1 = (nr4.z-nr4.x)*(nr4.w-nr4.y);
        float best = -1.0f; int bi = 0;
        #pragma unroll 4
        for (int t = 0; t < T_; t++) {
            float bt = sb[t*4+0], bl = sb[t*4+1], bb = sb[t*4+2], br = sb[t*4+3];
            float inter = fmaxf(fminf(bb,nr4.z)-fmaxf(bt,nr4.x),0.f)
                        * fmaxf(fminf(br,nr4.w)-fmaxf(bl,nr4.y),0.f);
            float a2 = (bb-bt)*(br-bl);
            float iou = inter / (area1 + a2 - inter);
            if (iou > best) { best = iou; bi = t; }
        }
        g_ioum[b*R_+r] = best;
        g_ridx[b*R_+r] = bi;
    }
}

// ---------------- RPN selection: parallel first-K compaction ----------------
__global__ void rpn_count_kernel() {
    __shared__ int sP[32];
    int c = blockIdx.x, tid = threadIdx.x, lane = tid & 31, wid = tid >> 5;
    int cp = 0;
    #pragma unroll
    for (int i = 0; i < 8; i++) {
        float v = g_maxiou[c*8192 + i*1024 + tid];
        cp += (v > 0.5f) ? 1 : 0;
    }
    #pragma unroll
    for (int d = 16; d; d >>= 1) cp += __shfl_down_sync(0xffffffffu, cp, d);
    if (lane == 0) sP[wid] = cp;
    __syncthreads();
    if (wid == 0) {
        int s = sP[lane];
        #pragma unroll
        for (int d = 16; d; d >>= 1) s += __shfl_down_sync(0xffffffffu, s, d);
        if (lane == 0) { g_cntP[c] = s; g_cntN[c] = 8192 - s; }
    }
}

__global__ void rpn_prefix_kernel() {
    if (threadIdx.x == 0) {
        int ap = 0, an = 0;
        for (int c = 0; c < 18; c++) {
            g_offP[c] = ap; g_offN[c] = an;
            ap += g_cntP[c]; an += g_cntN[c];
        }
    }
}

__global__ void rpn_place_kernel() {
    __shared__ int sCntP[32], sCntN[32], sOffP[32], sOffN[32];
    __shared__ int sTotP, sTotN;
    int c = blockIdx.x, tid = threadIdx.x, lane = tid & 31, wid = tid >> 5;
    int baseP = g_offP[c], baseN = g_offN[c];
    if (baseP >= 128 && baseN >= 252) return;
    for (int ph = 0; ph < 8; ph++) {
        int j = c*8192 + ph*1024 + tid;
        float v = g_maxiou[j];
        bool fp = (v > 0.5f), fn = !fp;
        unsigned mp = __ballot_sync(0xffffffffu, fp);
        unsigned mn = __ballot_sync(0xffffffffu, fn);
        if (lane == 0) { sCntP[wid] = __popc(mp); sCntN[wid] = __popc(mn); }
        __syncthreads();
        if (wid == 0) {
            int cp = sCntP[lane], cn = sCntN[lane];
            int sp = cp, sn = cn;
            #pragma unroll
            for (int d = 1; d < 32; d <<= 1) {
                int tp = __shfl_up_sync(0xffffffffu, sp, d);
                int tn = __shfl_up_sync(0xffffffffu, sn, d);
                if (lane >= d) { sp += tp; sn += tn; }
            }
            sOffP[lane] = sp - cp; sOffN[lane] = sn - cn;
            if (lane == 31) { sTotP = sp; sTotN = sn; }
        }
        __syncthreads();
        if (fp) {
            int p = baseP + sOffP[wid] + __popc(mp & ((1u << lane) - 1u));
            if (p < 128) g_pos[p] = j;
        }
        if (fn) {
            int p = baseN + sOffN[wid] + __popc(mn & ((1u << lane) - 1u));
            if (p < 252) g_neg[p] = j;
        }
        baseP += sTotP; baseN += sTotN;
        __syncthreads();
        if (baseP >= 128 && baseN >= 252) return;
    }
}

// ---------------- topk(192) radix-select + posr first-64 ----------------
__global__ void topk_posr_kernel() {
    __shared__ float sv[B_*R_];
    __shared__ int hist[256];
    __shared__ int sCnt[32], sOff[32];
    __shared__ int sTot;
    __shared__ unsigned sPrefix;
    __shared__ int sRemain, sCntG;
    int tid = threadIdx.x, lane = tid & 31, wid = tid >> 5;

    for (int j = tid; j < B_*R_; j += 1024) {
        float v = g_ioum[j];
        sv[j] = (v <= 0.5f) ? v : -INFINITY;
    }
    if (tid == 0) { sPrefix = 0; sRemain = NNEG_; sCntG = 0; }
    __syncthreads();

    // posr: first 64 with iou > 0.5, index order
    int base = 0;
    for (int ph = 0; ph < 8 && base < NPOS_; ph++) {
        int j = ph*1024 + tid;
        bool f = (j < B_*R_) && (g_ioum[j] > 0.5f);
        unsigned m = __ballot_sync(0xffffffffu, f);
        if (lane == 0) sCnt[wid] = __popc(m);
        __syncthreads();
        if (wid == 0) {
            int cp = sCnt[lane], sp = cp;
            #pragma unroll
            for (int d = 1; d < 32; d <<= 1) {
                int tp = __shfl_up_sync(0xffffffffu, sp, d);
                if (lane >= d) sp += tp;
            }
            sOff[lane] = sp - cp;
            if (lane == 31) sTot = sp;
        }
        __syncthreads();
        if (f) {
            int p = base + sOff[wid] + __popc(m & ((1u << lane) - 1u));
            if (p < NPOS_) g_posr[p] = j;
        }
        base += sTot;
        __syncthreads();
    }

    // radix select threshold key (top-192, ties -> lowest index)
    for (int lvl = 24; lvl >= 0; lvl -= 8) {
        if (tid < 256) hist[tid] = 0;
        __syncthreads();
        unsigned pfx = sPrefix;
        for (int j = tid; j < B_*R_; j += 1024) {
            unsigned k = fkey(sv[j]);
            bool match = (lvl == 24) || ((k >> (lvl+8)) == pfx);
            if (match) atomicAdd(&hist[(k >> lvl) & 255], 1);
        }
        __syncthreads();
        if (tid == 0) {
            int need = sRemain, acc = 0, b = 255;
            for (; b > 0; b--) {
                if (acc + hist[b] >= need) break;
                acc += hist[b];
            }
            sPrefix = (pfx << 8) | (unsigned)b;
            sRemain = need - acc;
        }
        __syncthreads();
    }
    unsigned K = sPrefix;
    int needEq = sRemain;
    int G = NNEG_ - needEq;

    // strictly greater: set-only, atomic append
    for (int j = tid; j < B_*R_; j += 1024) {
        if (fkey(sv[j]) > K) {
            int p = atomicAdd(&sCntG, 1);
            g_negr[p] = j;
        }
    }
    __syncthreads();
    // equals: lowest needEq indices, ordered
    base = 0;
    for (int ph = 0; ph < 8 && base < needEq; ph++) {
        int j = ph*1024 + tid;
        bool f = (j < B_*R_) && (fkey(sv[j]) == K);
        unsigned m = __ballot_sync(0xffffffffu, f);
        if (lane == 0) sCnt[wid] = __popc(m);
        __syncthreads();
        if (wid == 0) {
            int cp = sCnt[lane], sp = cp;
            #pragma unroll
            for (int d = 1; d < 32; d <<= 1) {
                int tp = __shfl_up_sync(0xffffffffu, sp, d);
                if (lane >= d) sp += tp;
            }
            sOff[lane] = sp - cp;
            if (lane == 31) sTot = sp;
        }
        __syncthreads();
        if (f) {
            int p = base + sOff[wid] + __popc(m & ((1u << lane) - 1u));
            if (p < needEq) g_negr[G + p] = j;
        }
        base += sTot;
        __syncthreads();
    }
}

// ---------------- ROI pool -> bf16 hi/lo feature matrix ----------------
__global__ void roi_pool_kernel(const float* __restrict__ nms_reg) {
    int j = blockIdx.x;
    int c = threadIdx.x;
    int sel = (j < NPOS_) ? g_posr[j] : g_negr[j - NPOS_];
    int b = sel / R_;
    float t  = nms_reg[sel*4+0], l = nms_reg[sel*4+1];
    float bb = nms_reg[sel*4+2], r = nms_reg[sel*4+3];
    const float* fb = g_fmt + (size_t)b * H_ * W_ * C_;
    for (int p = 0; p < PP_*PP_; p++) {
        int py = p / PP_, px = p % PP_;
        float gy = (py + 0.5f) / (float)PP_;
        float gx = (px + 0.5f) / (float)PP_;
        float y = fminf(fmaxf(t + gy * (bb - t), 0.f), (float)(H_-1));
        float x = fminf(fmaxf(l + gx * (r  - l), 0.f), (float)(W_-1));
        int y0 = (int)floorf(y), x0 = (int)floorf(x);
        int y1 = min(y0 + 1, H_-1), x1 = min(x0 + 1, W_-1);
        float wy = y - (float)y0, wx = x - (float)x0;
        float v00 = fb[(y0*W_+x0)*C_ + c];
        float v01 = fb[(y0*W_+x1)*C_ + c];
        float v10 = fb[(y1*W_+x0)*C_ + c];
        float v11 = fb[(y1*W_+x1)*C_ + c];
        float v = v00*(1.f-wy)*(1.f-wx) + v01*(1.f-wy)*wx
                + v10*wy*(1.f-wx)       + v11*wy*wx;
        __nv_bfloat16 h = __float2bfloat16(v);
        int o = j*D_ + p*C_ + c;
        g_Ahi[o] = h;
        g_Alo[o] = __float2bfloat16(v - __bfloat162float(h));
    }
}

// ---------------- mma.sync GEMM: BM128 BN64 BK32, 3-stage, split-K=8 ----------------
__device__ __forceinline__ void ldsm_x4(uint32_t* r, uint32_t addr) {
    asm volatile("ldmatrix.sync.aligned.m8n8.x4.shared.b16 {%0,%1,%2,%3}, [%4];"
        : "=r"(r[0]), "=r"(r[1]), "=r"(r[2]), "=r"(r[3]) : "r"(addr));
}
__device__ __forceinline__ void mma16816(float* d, const uint32_t* a, const uint32_t* b) {
    asm volatile("mma.sync.aligned.m16n8k16.row.col.f32.bf16.bf16.f32 "
        "{%0,%1,%2,%3}, {%4,%5,%6,%7}, {%8,%9}, {%0,%1,%2,%3};"
        : "+f"(d[0]), "+f"(d[1]), "+f"(d[2]), "+f"(d[3])
        : "r"(a[0]), "r"(a[1]), "r"(a[2]), "r"(a[3]), "r"(b[0]), "r"(b[1]));
}
__device__ __forceinline__ void cp16(uint32_t saddr, const void* gaddr) {
    asm volatile("cp.async.cg.shared.global [%0], [%1], 16;" :: "r"(saddr), "l"(gaddr));
}

__global__ void __launch_bounds__(256, 2) gemm_mma_kernel() {
    extern __shared__ char smem[];
    uint32_t sb = smem_u32(smem);
    int tid = threadIdx.x, wid = tid >> 5, lane = tid & 31;
    int n0 = blockIdx.x * 64;
    int m0 = blockIdx.y * 128;
    int kt = blockIdx.z;
    int kbase = kt * KPC_;
    int wm = wid >> 1, wn = wid & 1;     // warp tile 32x32

    const uint4* bAhi = (const uint4*)g_Ahi + (size_t)m0 * (D_/8);
    const uint4* bAlo = (const uint4*)g_Alo + (size_t)m0 * (D_/8);
    const uint4* bBhi = (const uint4*)g_Bhi + (size_t)n0 * (D_/8);
    const uint4* bBlo = (const uint4*)g_Blo + (size_t)n0 * (D_/8);

    // A tiles: 512 16B-chunks each (2 per thread); B tiles: 256 (1 per thread)
    int a0r = tid >> 2,          a0q = tid & 3;
    int a1r = (tid + 256) >> 2,  a1q = tid & 3;
    int b0r = tid >> 2,          b0q = tid & 3;

    auto load_stage = [&](int it) {
        uint32_t sg = sb + (it % NSTG_) * STAGE_;
        int kq = (kbase + it*BK_) >> 3;
        cp16(sg +            a0r*80 + a0q*16, bAhi + (size_t)a0r*(D_/8) + kq + a0q);
        cp16(sg +            a1r*80 + a1q*16, bAhi + (size_t)a1r*(D_/8) + kq + a1q);
        cp16(sg + ATILE_   + a0r*80 + a0q*16, bAlo + (size_t)a0r*(D_/8) + kq + a0q);
        cp16(sg + ATILE_   + a1r*80 + a1q*16, bAlo + (size_t)a1r*(D_/8) + kq + a1q);
        cp16(sg + 2*ATILE_ + b0r*80 + b0q*16, bBhi + (size_t)b0r*(D_/8) + kq + b0q);
        cp16(sg + 2*ATILE_ + BTILE_ + b0r*80 + b0q*16, bBlo + (size_t)b0r*(D_/8) + kq + b0q);
        asm volatile("cp.async.commit_group;");
    };

    float acc[2][4][4];
    #pragma unroll
    for (int i = 0; i < 2; i++)
        #pragma unroll
        for (int j = 0; j < 4; j++)
            #pragma unroll
            for (int q = 0; q < 4; q++) acc[i][j][q] = 0.f;

    load_stage(0);
    load_stage(1);

    for (int it = 0; it < NIT_; it++) {
        asm volatile("cp.async.wait_group 1;");
        __syncthreads();
        if (it + 2 < NIT_) load_stage(it + 2);
        else asm volatile("cp.async.commit_group;");

        uint32_t sg = sb + (it % NSTG_) * STAGE_;
        uint32_t aHiB = sg, aLoB = sg + ATILE_;
        uint32_t bHiB = sg + 2*ATILE_, bLoB = bHiB + BTILE_;

        #pragma unroll
        for (int ks = 0; ks < 2; ks++) {
            int acol = ks*16 + ((lane >> 4) & 1) * 8;
            uint32_t ahi[2][4], alo[2][4], bhi[4][2], blo[4][2];
            #pragma unroll
            for (int mt = 0; mt < 2; mt++) {
                int arow = wm*32 + mt*16 + (lane & 15);
                uint32_t off = arow*80 + acol*2;
                ldsm_x4(ahi[mt], aHiB + off);
                ldsm_x4(alo[mt], aLoB + off);
            }
            #pragma unroll
            for (int p = 0; p < 2; p++) {
                int brow = wn*32 + (p*2 + ((lane >> 4) & 1))*8 + (lane & 7);
                uint32_t off = brow*80 + (ks*16 + ((lane >> 3) & 1)*8)*2;
                uint32_t r4[4];
                ldsm_x4(r4, bHiB + off);
                bhi[p*2][0] = r4[0]; bhi[p*2][1] = r4[1];
                bhi[p*2+1][0] = r4[2]; bhi[p*2+1][1] = r4[3];
                ldsm_x4(r4, bLoB + off);
                blo[p*2][0] = r4[0]; blo[p*2][1] = r4[1];
                blo[p*2+1][0] = r4[2]; blo[p*2+1][1] = r4[3];
            }
            #pragma unroll
            for (int mt = 0; mt < 2; mt++)
                #pragma unroll
                for (int nt = 0; nt < 4; nt++) {
                    mma16816(acc[mt][nt], ahi[mt], bhi[nt]);
                    mma16816(acc[mt][nt], ahi[mt], blo[nt]);
                    mma16816(acc[mt][nt], alo[mt], bhi[nt]);
                }
        }
    }

    // epilogue: write split-K partials
    float* outp = g_partial[kt];
    int g = lane >> 2, qc = (lane & 3) * 2;
    #pragma unroll
    for (int mt = 0; mt < 2; mt++) {
        #pragma unroll
        for (int nt = 0; nt < 4; nt++) {
            int row = m0 + wm*32 + mt*16 + g;
            int col = n0 + wn*32 + nt*8 + qc;
            *(float2*)&outp[(size_t)row*DH_ + col]     = make_float2(acc[mt][nt][0], acc[mt][nt][1]);
            *(float2*)&outp[(size_t)(row+8)*DH_ + col] = make_float2(acc[mt][nt][2], acc[mt][nt][3]);
        }
    }
}

// ---------------- reduce partials + bias + relu ----------------
__global__ void reduce_bias_relu_kernel(const float* __restrict__ b1) {
    int i4 = blockIdx.x * 256 + threadIdx.x;
    const float4* b4 = (const float4*)b1;
    float4 s = b4[i4 & 255];
    #pragma unroll
    for (int k = 0; k < KT_; k++) {
        float4 p = ((const float4*)g_partial[k])[i4];
        s.x += p.x; s.y += p.y; s.z += p.z; s.w += p.w;
    }
    float4 o;
    o.x = fmaxf(s.x, 0.f); o.y = fmaxf(s.y, 0.f);
    o.z = fmaxf(s.z, 0.f); o.w = fmaxf(s.w, 0.f);
    ((float4*)g_hmid)[i4] = o;
}

// ---------------- heads ----------------
__global__ void heads_kernel(const float* __restrict__ Wr, const float* __restrict__ br,
                             const float* __restrict__ Wc, const float* __restrict__ bc) {
    __shared__ float h[DH_];
    int row = blockIdx.x;
    int tid = threadIdx.x;
    for (int k = tid; k < DH_; k += 128) h[k] = g_hmid[(size_t)row * DH_ + k];
    __syncthreads();
    int wid = tid >> 5, lane = tid & 31;
    for (int o = wid; o < 4 + NCLS_; o += 4) {
        float s = 0.f;
        if (o < 4) {
            for (int k = lane; k < DH_; k += 32) s += h[k] * Wr[k*4 + o];
        } else {
            int oc = o - 4;
            for (int k = lane; k < DH_; k += 32) s += h[k] * Wc[k*NCLS_ + oc];
        }
        #pragma unroll
        for (int d = 16; d; d >>= 1) s += __shfl_down_sync(0xffffffffu, s, d);
        if (lane == 0) {
            if (o < 4) g_rreg[row*4 + o] = s + br[o];
            else       g_rcls[row*NCLS_ + (o-4)] = s + bc[o-4];
        }
    }
}

// ---------------- finalize ----------------
__device__ float blockReduceSum512(float v, float* sbuf) {
    int tid = threadIdx.x;
    sbuf[tid] = v; __syncthreads();
    for (int s = 256; s > 0; s >>= 1) {
        if (tid < s) sbuf[tid] += sbuf[tid + s];
        __syncthreads();
    }
    float r = sbuf[0]; __syncthreads();
    return r;
}

__global__ void finalize_kernel(const float* __restrict__ nms_reg,
                                const float* __restrict__ bboxes,
                                const int*   __restrict__ classes,
                                const float* __restrict__ anchors,
                                const float* __restrict__ rpn_reg,
                                const float* __restrict__ rpn_cls,
                                float* __restrict__ out) {
    __shared__ float sbuf[512];
    int tid = threadIdx.x;

    float a = 0.f;
    if (tid < 380) {
        int i = (tid < 128) ? g_pos[tid] : g_neg[tid - 128];
        float x = rpn_cls[i];
        float lbl = (tid < 128) ? 1.f : 0.f;
        a = fmaxf(x, 0.f) - x * lbl + log1pf(expf(-fabsf(x)));
    }
    float rpnCls = blockReduceSum512(a, sbuf) / 380.f;

    float bsum = 0.f;
    {
        int jj = tid >> 2, c = tid & 3;
        int i = g_pos[jj];
        int b = i / A_;
        int aidx = i - b * A_;
        float pred = rpn_reg[i*4 + c];
        float tgt = bboxes[(b*T_ + g_tidx[i])*4 + c] - anchors[aidx*4 + c];
        float d = fabsf(pred - tgt);
        bsum = (d < 1.f) ? 0.5f*d*d : d - 0.5f;
    }
    float rpnReg = blockReduceSum512(bsum, sbuf) / 512.f / 4.f;

    float csum = 0.f, accsum = 0.f;
    if (tid < 256) {
        int j = tid;
        int cls = 0;
        if (j < NPOS_) {
            int i = g_posr[j];
            int b = i / R_;
            cls = classes[b*T_ + g_ridx[i]];
        }
        const float* row = &g_rcls[j*NCLS_];
        float mx = row[0];
        #pragma unroll
        for (int c = 1; c < NCLS_; c++) mx = fmaxf(mx, row[c]);
        float se = 0.f;
        #pragma unroll
        for (int c = 0; c < NCLS_; c++) se += expf(row[c] - mx);
        float lse = mx + logf(se);
        csum = lse - row[cls];
        if (j < NPOS_) {
            int am = 0; float bv = row[0];
            #pragma unroll
            for (int c = 1; c < NCLS_; c++) if (row[c] > bv) { bv = row[c]; am = c; }
            accsum = (am == cls) ? 1.f : 0.f;
        }
    }
    float rcnnCls = blockReduceSum512(csum, sbuf) / 256.f;
    float acc     = blockReduceSum512(accsum, sbuf) / (float)NPOS_;

    float dsl = 0.f, dab = 0.f;
    if (tid < NPOS_*4) {
        int jj = tid >> 2, c = tid & 3;
        int i = g_posr[jj];
        int b = i / R_;
        float v = nms_reg[i*4 + c];
        float rounded = (c < 2) ? floorf(v * 16.f) / 16.f : ceilf(v * 16.f) / 16.f;
        float mb = bboxes[(b*T_ + g_ridx[i])*4 + c];
        float tgt = mb - rounded;
        float pr = g_rreg[jj*4 + c];
        float d = fabsf(pr - tgt);
        dsl = (d < 1.f) ? 0.5f*d*d : d - 0.5f;
        dab = d;
    }
    float rcnnReg = blockReduceSum512(dsl, sbuf) / (float)NPOS_ / 4.f;
    float offset  = blockReduceSum512(dab, sbuf) / (float)NPOS_ / 4.f;

    if (tid == 0) {
        out[0] = rpnCls;
        out[1] = rpnReg;
        out[2] = rcnnCls;
        out[3] = rcnnReg;
        out[4] = acc;
        out[5] = offset;
    }
}

// ---------------- launch ----------------
extern "C" void kernel_launch(void* const* d_in, const int* in_sizes, int n_in,
                              void* d_out, int out_size) {
    const float* nms_reg  = (const float*)d_in[0];
    const float* fm       = (const float*)d_in[2];
    const float* bboxes   = (const float*)d_in[3];
    const int*   classes  = (const int*)  d_in[4];
    const float* anchors  = (const float*)d_in[5];
    const float* rpn_reg  = (const float*)d_in[6];
    const float* rpn_cls  = (const float*)d_in[7];
    const float* W1       = (const float*)d_in[8];
    const float* b1       = (const float*)d_in[9];
    const float* Wr       = (const float*)d_in[10];
    const float* br       = (const float*)d_in[11];
    const float* Wc       = (const float*)d_in[12];
    const float* bc       = (const float*)d_in[13];
    float* out = (float*)d_out;

    cudaFuncSetAttribute(gemm_mma_kernel, cudaFuncAttributeMaxDynamicSharedMemorySize, SMEM_GEMM_);

    init_sel_kernel<<<1, 512>>>();
    prep_kernel<<<PB_TOTAL, 256>>>(W1, fm, bboxes, anchors, nms_reg);
    rpn_count_kernel<<<18, 1024>>>();
    rpn_prefix_kernel<<<1, 32>>>();
    rpn_place_kernel<<<18, 1024>>>();
    topk_posr_kernel<<<1, 1024>>>();
    roi_pool_kernel<<<256, 256>>>(nms_reg);
    gemm_mma_kernel<<<dim3(16, 2, KT_), 256, SMEM_GEMM_>>>();
    reduce_bias_relu_kernel<<<256, 256>>>(b1);
    heads_kernel<<<256, 128>>>(Wr, br, Wc, bc);
    finalize_kernel<<<1, 512>>>(nms_reg, bboxes, classes, anchors, rpn_reg, rpn_cls, out);
}

// round 5
// speedup vs baseline: 3.1985x; 1.0950x over previous
#include <cuda_runtime.h>
#include <cuda_bf16.h>
#include <math.h>
#include <stdint.h>

#define B_ 4
#define T_ 40
#define R_ 2000
#define A_ 36864
#define H_ 64
#define W_ 64
#define C_ 256
#define PP_ 7
#define NCLS_ 21
#define NPOS_ 64
#define NNEG_ 192
#define DH_ 1024
#define D_ (PP_*PP_*C_)   // 12544
#define KT_ 8             // split-K factor
#define KPC_ (D_/KT_)     // 1568 per CTA
#define BK_ 32
#define NIT_ (KPC_/BK_)   // 49

// GEMM smem: A tiles bf16 rows padded to 40 elems (80B); B tile fp32 rows padded to 68 words
#define TPAD_ 40
#define ATILE_ (128*TPAD_*2)            // 10240
#define BPADW_ 68
#define BTILEF_ (32*BPADW_*4)           // 8704
#define STAGE_ (2*ATILE_ + BTILEF_)     // 29184
#define NSTG_ 3
#define SMEM_GEMM_ (NSTG_*STAGE_)       // 87552

// ---------------- scratch ----------------
__device__ float g_fmt[B_*H_*W_*C_];
__device__ float g_maxiou[B_*A_];
__device__ int   g_tidx[B_*A_];
__device__ float g_ioum[B_*R_];
__device__ int   g_ridx[B_*R_];
__device__ int   g_pos[128];
__device__ int   g_neg[252];
__device__ int   g_posr[NPOS_];
__device__ int   g_negr[NNEG_];
__device__ int   g_cntP[18], g_cntN[18];
__device__ __nv_bfloat16 g_Ahi[256*D_];
__device__ __nv_bfloat16 g_Alo[256*D_];
__device__ float g_partial[KT_][256*DH_];
__device__ float g_hmid[256*DH_];
__device__ float g_rreg[256*4];
__device__ float g_rcls[256*NCLS_];

__device__ __forceinline__ uint32_t smem_u32(const void* p) {
    uint32_t a;
    asm("{ .reg .u64 t; cvta.to.shared.u64 t, %1; cvt.u32.u64 %0, t; }" : "=r"(a) : "l"(p));
    return a;
}
__device__ __forceinline__ unsigned fkey(float f) {
    unsigned u = __float_as_uint(f);
    return (u & 0x80000000u) ? ~u : (u | 0x80000000u);
}

// ---------------- fused prep: init | transpose | rpn_iou | rcnn_iou ----------------
#define PB_TRANS 4096                   // 2*8*256
#define PB_RPN   576                    // 144*4
#define PB_RCNN  32                     // 8*4
#define PB_TOTAL (PB_TRANS + PB_RPN + PB_RCNN + 1)

__global__ void prep_kernel(const float* __restrict__ fm,
                            const float* __restrict__ bboxes,
                            const float* __restrict__ anchors,
                            const float* __restrict__ nms_reg) {
    __shared__ float tile[32][33];
    int blk = blockIdx.x;
    int tid = threadIdx.x;          // 256
    if (blk < PB_TRANS) {
        // NCHW -> NHWC
        int bh = blk >> 4;                      // 0..255  (b*H + y)
        int sub = blk & 15;                     // x-tile (2) * c-tile (8)
        int x0 = (sub & 1) * 32, c0 = (sub >> 1) * 32;
        int b = bh >> 6, y = bh & 63;
        int tx = tid & 31, ty = tid >> 5;       // 32 x 8
        #pragma unroll
        for (int i = 0; i < 4; i++) {
            int c = c0 + ty + i*8;
            tile[ty + i*8][tx] = fm[((b*C_ + c)*H_ + y)*W_ + x0 + tx];
        }
        __syncthreads();
        #pragma unroll
        for (int i = 0; i < 4; i++) {
            int xr = ty + i*8;
            g_fmt[((b*H_ + y)*W_ + x0+xr)*C_ + c0+tx] = tile[tx][xr];
        }
        return;
    }
    blk -= PB_TRANS;
    if (blk < PB_RPN) {
        int b = blk / 144, bx = blk % 144;
        float* sb = &tile[0][0];
        if (tid < T_*4) sb[tid] = bboxes[b*T_*4 + tid];
        __syncthreads();
        int a = bx*256 + tid;
        float4 an = ((const float4*)anchors)[a];
        float area2 = (an.z-an.x)*(an.w-an.y);
        float best = -1.0f; int bi = 0;
        #pragma unroll 4
        for (int t = 0; t < T_; t++) {
            float bt = sb[t*4+0], bl = sb[t*4+1], bb = sb[t*4+2], br = sb[t*4+3];
            float inter = fmaxf(fminf(bb,an.z)-fmaxf(bt,an.x),0.f)
                        * fmaxf(fminf(br,an.w)-fmaxf(bl,an.y),0.f);
            float a1 = (bb-bt)*(br-bl);
            float iou = inter / (a1 + area2 - inter);
            if (iou > best) { best = iou; bi = t; }
        }
        g_maxiou[b*A_+a] = best;
        g_tidx[b*A_+a] = bi;
        return;
    }
    blk -= PB_RPN;
    if (blk < PB_RCNN) {
        int b = blk >> 3, rx = blk & 7;
        float* sb = &tile[0][0];
        if (tid < T_*4) sb[tid] = bboxes[b*T_*4 + tid];
        __syncthreads();
        int r = rx*256 + tid;
        if (r >= R_) return;
        float4 nr4 = ((const float4*)nms_reg)[b*R_+r];
        float area1 = (nr4.z-nr4.x)*(nr4.w-nr4.y);
        float best = -1.0f; int bi = 0;
        #pragma unroll 4
        for (int t = 0; t < T_; t++) {
            float bt = sb[t*4+0], bl = sb[t*4+1], bb = sb[t*4+2], br = sb[t*4+3];
            float inter = fmaxf(fminf(bb,nr4.z)-fmaxf(bt,nr4.x),0.f)
                        * fmaxf(fminf(br,nr4.w)-fmaxf(bl,nr4.y),0.f);
            float a2 = (bb-bt)*(br-bl);
            float iou = inter / (area1 + a2 - inter);
            if (iou > best) { best = iou; bi = t; }
        }
        g_ioum[b*R_+r] = best;
        g_ridx[b*R_+r] = bi;
        return;
    }
    // init block
    if (tid < 128)  g_pos[tid]  = 0;
    if (tid < 252)  g_neg[tid]  = 0;
    if (tid < NPOS_) g_posr[tid] = 0;
}

// ---------------- RPN selection: parallel first-K compaction ----------------
__global__ void rpn_count_kernel() {
    __shared__ int sP[32];
    int c = blockIdx.x, tid = threadIdx.x, lane = tid & 31, wid = tid >> 5;
    int cp = 0;
    #pragma unroll
    for (int i = 0; i < 8; i++) {
        float v = g_maxiou[c*8192 + i*1024 + tid];
        cp += (v > 0.5f) ? 1 : 0;
    }
    #pragma unroll
    for (int d = 16; d; d >>= 1) cp += __shfl_down_sync(0xffffffffu, cp, d);
    if (lane == 0) sP[wid] = cp;
    __syncthreads();
    if (wid == 0) {
        int s = sP[lane];
        #pragma unroll
        for (int d = 16; d; d >>= 1) s += __shfl_down_sync(0xffffffffu, s, d);
        if (lane == 0) { g_cntP[c] = s; g_cntN[c] = 8192 - s; }
    }
}

__global__ void rpn_place_kernel() {
    __shared__ int sCntP[32], sCntN[32], sOffP[32], sOffN[32];
    __shared__ int sTotP, sTotN;
    int c = blockIdx.x, tid = threadIdx.x, lane = tid & 31, wid = tid >> 5;
    // inline prefix over 18 chunk counts
    int baseP = 0, baseN = 0;
    for (int i = 0; i < c; i++) { baseP += g_cntP[i]; baseN += g_cntN[i]; }
    if (baseP >= 128 && baseN >= 252) return;
    for (int ph = 0; ph < 8; ph++) {
        int j = c*8192 + ph*1024 + tid;
        float v = g_maxiou[j];
        bool fp = (v > 0.5f), fn = !fp;
        unsigned mp = __ballot_sync(0xffffffffu, fp);
        unsigned mn = __ballot_sync(0xffffffffu, fn);
        if (lane == 0) { sCntP[wid] = __popc(mp); sCntN[wid] = __popc(mn); }
        __syncthreads();
        if (wid == 0) {
            int cp = sCntP[lane], cn = sCntN[lane];
            int sp = cp, sn = cn;
            #pragma unroll
            for (int d = 1; d < 32; d <<= 1) {
                int tp = __shfl_up_sync(0xffffffffu, sp, d);
                int tn = __shfl_up_sync(0xffffffffu, sn, d);
                if (lane >= d) { sp += tp; sn += tn; }
            }
            sOffP[lane] = sp - cp; sOffN[lane] = sn - cn;
            if (lane == 31) { sTotP = sp; sTotN = sn; }
        }
        __syncthreads();
        if (fp) {
            int p = baseP + sOffP[wid] + __popc(mp & ((1u << lane) - 1u));
            if (p < 128) g_pos[p] = j;
        }
        if (fn) {
            int p = baseN + sOffN[wid] + __popc(mn & ((1u << lane) - 1u));
            if (p < 252) g_neg[p] = j;
        }
        baseP += sTotP; baseN += sTotN;
        __syncthreads();
        if (baseP >= 128 && baseN >= 252) return;
    }
}

// ---------------- topk(192) radix-select + posr first-64 ----------------
__global__ void topk_posr_kernel() {
    __shared__ float sv[B_*R_];
    __shared__ int hist[256];
    __shared__ int sCnt[32], sOff[32];
    __shared__ int sTot;
    __shared__ unsigned sPrefix;
    __shared__ int sRemain, sCntG;
    int tid = threadIdx.x, lane = tid & 31, wid = tid >> 5;

    for (int j = tid; j < B_*R_; j += 1024) {
        float v = g_ioum[j];
        sv[j] = (v <= 0.5f) ? v : -INFINITY;
    }
    if (tid == 0) { sPrefix = 0; sRemain = NNEG_; sCntG = 0; }
    __syncthreads();

    // posr: first 64 with iou > 0.5, index order
    int base = 0;
    for (int ph = 0; ph < 8 && base < NPOS_; ph++) {
        int j = ph*1024 + tid;
        bool f = (j < B_*R_) && (g_ioum[j] > 0.5f);
        unsigned m = __ballot_sync(0xffffffffu, f);
        if (lane == 0) sCnt[wid] = __popc(m);
        __syncthreads();
        if (wid == 0) {
            int cp = sCnt[lane], sp = cp;
            #pragma unroll
            for (int d = 1; d < 32; d <<= 1) {
                int tp = __shfl_up_sync(0xffffffffu, sp, d);
                if (lane >= d) sp += tp;
            }
            sOff[lane] = sp - cp;
            if (lane == 31) sTot = sp;
        }
        __syncthreads();
        if (f) {
            int p = base + sOff[wid] + __popc(m & ((1u << lane) - 1u));
            if (p < NPOS_) g_posr[p] = j;
        }
        base += sTot;
        __syncthreads();
    }

    // radix select threshold key (top-192, ties -> lowest index)
    for (int lvl = 24; lvl >= 0; lvl -= 8) {
        if (tid < 256) hist[tid] = 0;
        __syncthreads();
        unsigned pfx = sPrefix;
        for (int j = tid; j < B_*R_; j += 1024) {
            unsigned k = fkey(sv[j]);
            bool match = (lvl == 24) || ((k >> (lvl+8)) == pfx);
            if (match) atomicAdd(&hist[(k >> lvl) & 255], 1);
        }
        __syncthreads();
        if (tid == 0) {
            int need = sRemain, acc = 0, b = 255;
            for (; b > 0; b--) {
                if (acc + hist[b] >= need) break;
                acc += hist[b];
            }
            sPrefix = (pfx << 8) | (unsigned)b;
            sRemain = need - acc;
        }
        __syncthreads();
    }
    unsigned K = sPrefix;
    int needEq = sRemain;
    int G = NNEG_ - needEq;

    // strictly greater: set-only, atomic append
    for (int j = tid; j < B_*R_; j += 1024) {
        if (fkey(sv[j]) > K) {
            int p = atomicAdd(&sCntG, 1);
            g_negr[p] = j;
        }
    }
    __syncthreads();
    // equals: lowest needEq indices, ordered
    base = 0;
    for (int ph = 0; ph < 8 && base < needEq; ph++) {
        int j = ph*1024 + tid;
        bool f = (j < B_*R_) && (fkey(sv[j]) == K);
        unsigned m = __ballot_sync(0xffffffffu, f);
        if (lane == 0) sCnt[wid] = __popc(m);
        __syncthreads();
        if (wid == 0) {
            int cp = sCnt[lane], sp = cp;
            #pragma unroll
            for (int d = 1; d < 32; d <<= 1) {
                int tp = __shfl_up_sync(0xffffffffu, sp, d);
                if (lane >= d) sp += tp;
            }
            sOff[lane] = sp - cp;
            if (lane == 31) sTot = sp;
        }
        __syncthreads();
        if (f) {
            int p = base + sOff[wid] + __popc(m & ((1u << lane) - 1u));
            if (p < needEq) g_negr[G + p] = j;
        }
        base += sTot;
        __syncthreads();
    }
}

// ---------------- ROI pool -> bf16 hi/lo feature matrix ----------------
__global__ void roi_pool_kernel(const float* __restrict__ nms_reg) {
    int j = blockIdx.x;
    int c = threadIdx.x;
    int sel = (j < NPOS_) ? g_posr[j] : g_negr[j - NPOS_];
    int b = sel / R_;
    float t  = nms_reg[sel*4+0], l = nms_reg[sel*4+1];
    float bb = nms_reg[sel*4+2], r = nms_reg[sel*4+3];
    const float* fb = g_fmt + (size_t)b * H_ * W_ * C_;
    for (int p = 0; p < PP_*PP_; p++) {
        int py = p / PP_, px = p % PP_;
        float gy = (py + 0.5f) / (float)PP_;
        float gx = (px + 0.5f) / (float)PP_;
        float y = fminf(fmaxf(t + gy * (bb - t), 0.f), (float)(H_-1));
        float x = fminf(fmaxf(l + gx * (r  - l), 0.f), (float)(W_-1));
        int y0 = (int)floorf(y), x0 = (int)floorf(x);
        int y1 = min(y0 + 1, H_-1), x1 = min(x0 + 1, W_-1);
        float wy = y - (float)y0, wx = x - (float)x0;
        float v00 = fb[(y0*W_+x0)*C_ + c];
        float v01 = fb[(y0*W_+x1)*C_ + c];
        float v10 = fb[(y1*W_+x0)*C_ + c];
        float v11 = fb[(y1*W_+x1)*C_ + c];
        float v = v00*(1.f-wy)*(1.f-wx) + v01*(1.f-wy)*wx
                + v10*wy*(1.f-wx)       + v11*wy*wx;
        __nv_bfloat16 h = __float2bfloat16(v);
        int o = j*D_ + p*C_ + c;
        g_Ahi[o] = h;
        g_Alo[o] = __float2bfloat16(v - __bfloat162float(h));
    }
}

// ---------------- mma.sync GEMM: BM128 BN64 BK32, 3-stage, split-K=8 ----------------
// B (W1) staged as raw fp32, hi/lo bf16 fragments built on the fly.
__device__ __forceinline__ void ldsm_x4(uint32_t* r, uint32_t addr) {
    asm volatile("ldmatrix.sync.aligned.m8n8.x4.shared.b16 {%0,%1,%2,%3}, [%4];"
        : "=r"(r[0]), "=r"(r[1]), "=r"(r[2]), "=r"(r[3]) : "r"(addr));
}
__device__ __forceinline__ void mma16816(float* d, const uint32_t* a, const uint32_t* b) {
    asm volatile("mma.sync.aligned.m16n8k16.row.col.f32.bf16.bf16.f32 "
        "{%0,%1,%2,%3}, {%4,%5,%6,%7}, {%8,%9}, {%0,%1,%2,%3};"
        : "+f"(d[0]), "+f"(d[1]), "+f"(d[2]), "+f"(d[3])
        : "r"(a[0]), "r"(a[1]), "r"(a[2]), "r"(a[3]), "r"(b[0]), "r"(b[1]));
}
__device__ __forceinline__ void cp16(uint32_t saddr, const void* gaddr) {
    asm volatile("cp.async.cg.shared.global [%0], [%1], 16;" :: "r"(saddr), "l"(gaddr));
}

__global__ void __launch_bounds__(256, 2) gemm_mma_kernel(const float* __restrict__ W1) {
    extern __shared__ char smem[];
    uint32_t sb = smem_u32(smem);
    int tid = threadIdx.x, wid = tid >> 5, lane = tid & 31;
    int n0 = blockIdx.x * 64;
    int m0 = blockIdx.y * 128;
    int kt = blockIdx.z;
    int kbase = kt * KPC_;
    int wm = wid >> 1, wn = wid & 1;     // warp tile 32x32

    const uint4* bAhi = (const uint4*)g_Ahi + (size_t)m0 * (D_/8);
    const uint4* bAlo = (const uint4*)g_Alo + (size_t)m0 * (D_/8);

    // A tiles: 512 16B-chunks each (2 per thread)
    int a0r = tid >> 2,          a0q = tid & 3;
    int a1r = (tid + 256) >> 2,  a1q = tid & 3;
    // B fp32 tile [k=32][n=64]: 512 16B-chunks (2 per thread)
    int b0r = tid >> 4, b0q = tid & 15;

    auto load_stage = [&](int it) {
        uint32_t sg = sb + (it % NSTG_) * STAGE_;
        int kk = kbase + it*BK_;
        int kq = kk >> 3;
        cp16(sg +          a0r*80 + a0q*16, bAhi + (size_t)a0r*(D_/8) + kq + a0q);
        cp16(sg +          a1r*80 + a1q*16, bAhi + (size_t)a1r*(D_/8) + kq + a1q);
        cp16(sg + ATILE_ + a0r*80 + a0q*16, bAlo + (size_t)a0r*(D_/8) + kq + a0q);
        cp16(sg + ATILE_ + a1r*80 + a1q*16, bAlo + (size_t)a1r*(D_/8) + kq + a1q);
        uint32_t bg = sg + 2*ATILE_;
        cp16(bg + b0r*(BPADW_*4) + b0q*16,      W1 + (size_t)(kk + b0r)*DH_ + n0 + b0q*4);
        cp16(bg + (b0r+16)*(BPADW_*4) + b0q*16, W1 + (size_t)(kk + b0r+16)*DH_ + n0 + b0q*4);
        asm volatile("cp.async.commit_group;");
    };

    float acc[2][4][4];
    #pragma unroll
    for (int i = 0; i < 2; i++)
        #pragma unroll
        for (int j = 0; j < 4; j++)
            #pragma unroll
            for (int q = 0; q < 4; q++) acc[i][j][q] = 0.f;

    load_stage(0);
    load_stage(1);

    for (int it = 0; it < NIT_; it++) {
        asm volatile("cp.async.wait_group 1;");
        __syncthreads();
        if (it + 2 < NIT_) load_stage(it + 2);
        else asm volatile("cp.async.commit_group;");

        uint32_t sg = sb + (it % NSTG_) * STAGE_;
        uint32_t aHiB = sg, aLoB = sg + ATILE_;
        const float* sBf = (const float*)(smem + (it % NSTG_) * STAGE_ + 2*ATILE_);

        #pragma unroll
        for (int ks = 0; ks < 2; ks++) {
            int acol = ks*16 + ((lane >> 4) & 1) * 8;
            uint32_t ahi[2][4], alo[2][4], bhi[4][2], blo[4][2];
            #pragma unroll
            for (int mt = 0; mt < 2; mt++) {
                int arow = wm*32 + mt*16 + (lane & 15);
                uint32_t off = arow*80 + acol*2;
                ldsm_x4(ahi[mt], aHiB + off);
                ldsm_x4(alo[mt], aLoB + off);
            }
            // B fragments from fp32 smem, on-the-fly hi/lo split
            #pragma unroll
            for (int nt = 0; nt < 4; nt++) {
                int nn = wn*32 + nt*8 + (lane >> 2);
                #pragma unroll
                for (int rg = 0; rg < 2; rg++) {
                    int kk2 = ks*16 + (lane & 3)*2 + rg*8;
                    float v0 = sBf[(kk2+0)*BPADW_ + nn];
                    float v1 = sBf[(kk2+1)*BPADW_ + nn];
                    uint32_t hreg;
                    asm("cvt.rn.bf16x2.f32 %0, %1, %2;" : "=r"(hreg) : "f"(v1), "f"(v0));
                    float h0 = __uint_as_float(hreg << 16);
                    float h1 = __uint_as_float(hreg & 0xFFFF0000u);
                    uint32_t lreg;
                    asm("cvt.rn.bf16x2.f32 %0, %1, %2;" : "=r"(lreg) : "f"(v1-h1), "f"(v0-h0));
                    bhi[nt][rg] = hreg;
                    blo[nt][rg] = lreg;
                }
            }
            #pragma unroll
            for (int mt = 0; mt < 2; mt++)
                #pragma unroll
                for (int nt = 0; nt < 4; nt++) {
                    mma16816(acc[mt][nt], ahi[mt], bhi[nt]);
                    mma16816(acc[mt][nt], ahi[mt], blo[nt]);
                    mma16816(acc[mt][nt], alo[mt], bhi[nt]);
                }
        }
    }

    // epilogue: write split-K partials
    float* outp = g_partial[kt];
    int g = lane >> 2, qc = (lane & 3) * 2;
    #pragma unroll
    for (int mt = 0; mt < 2; mt++) {
        #pragma unroll
        for (int nt = 0; nt < 4; nt++) {
            int row = m0 + wm*32 + mt*16 + g;
            int col = n0 + wn*32 + nt*8 + qc;
            *(float2*)&outp[(size_t)row*DH_ + col]     = make_float2(acc[mt][nt][0], acc[mt][nt][1]);
            *(float2*)&outp[(size_t)(row+8)*DH_ + col] = make_float2(acc[mt][nt][2], acc[mt][nt][3]);
        }
    }
}

// ---------------- reduce partials + bias + relu ----------------
__global__ void reduce_bias_relu_kernel(const float* __restrict__ b1) {
    int i4 = blockIdx.x * 256 + threadIdx.x;
    const float4* b4 = (const float4*)b1;
    float4 s = b4[i4 & 255];
    #pragma unroll
    for (int k = 0; k < KT_; k++) {
        float4 p = ((const float4*)g_partial[k])[i4];
        s.x += p.x; s.y += p.y; s.z += p.z; s.w += p.w;
    }
    float4 o;
    o.x = fmaxf(s.x, 0.f); o.y = fmaxf(s.y, 0.f);
    o.z = fmaxf(s.z, 0.f); o.w = fmaxf(s.w, 0.f);
    ((float4*)g_hmid)[i4] = o;
}

// ---------------- heads ----------------
__global__ void heads_kernel(const float* __restrict__ Wr, const float* __restrict__ br,
                             const float* __restrict__ Wc, const float* __restrict__ bc) {
    __shared__ float h[DH_];
    int row = blockIdx.x;
    int tid = threadIdx.x;
    for (int k = tid; k < DH_; k += 128) h[k] = g_hmid[(size_t)row * DH_ + k];
    __syncthreads();
    int wid = tid >> 5, lane = tid & 31;
    for (int o = wid; o < 4 + NCLS_; o += 4) {
        float s = 0.f;
        if (o < 4) {
            for (int k = lane; k < DH_; k += 32) s += h[k] * Wr[k*4 + o];
        } else {
            int oc = o - 4;
            for (int k = lane; k < DH_; k += 32) s += h[k] * Wc[k*NCLS_ + oc];
        }
        #pragma unroll
        for (int d = 16; d; d >>= 1) s += __shfl_down_sync(0xffffffffu, s, d);
        if (lane == 0) {
            if (o < 4) g_rreg[row*4 + o] = s + br[o];
            else       g_rcls[row*NCLS_ + (o-4)] = s + bc[o-4];
        }
    }
}

// ---------------- finalize ----------------
__device__ float blockReduceSum512(float v, float* sbuf) {
    int tid = threadIdx.x;
    sbuf[tid] = v; __syncthreads();
    for (int s = 256; s > 0; s >>= 1) {
        if (tid < s) sbuf[tid] += sbuf[tid + s];
        __syncthreads();
    }
    float r = sbuf[0]; __syncthreads();
    return r;
}

__global__ void finalize_kernel(const float* __restrict__ nms_reg,
                                const float* __restrict__ bboxes,
                                const int*   __restrict__ classes,
                                const float* __restrict__ anchors,
                                const float* __restrict__ rpn_reg,
                                const float* __restrict__ rpn_cls,
                                float* __restrict__ out) {
    __shared__ float sbuf[512];
    int tid = threadIdx.x;

    float a = 0.f;
    if (tid < 380) {
        int i = (tid < 128) ? g_pos[tid] : g_neg[tid - 128];
        float x = rpn_cls[i];
        float lbl = (tid < 128) ? 1.f : 0.f;
        a = fmaxf(x, 0.f) - x * lbl + log1pf(expf(-fabsf(x)));
    }
    float rpnCls = blockReduceSum512(a, sbuf) / 380.f;

    float bsum = 0.f;
    {
        int jj = tid >> 2, c = tid & 3;
        int i = g_pos[jj];
        int b = i / A_;
        int aidx = i - b * A_;
        float pred = rpn_reg[i*4 + c];
        float tgt = bboxes[(b*T_ + g_tidx[i])*4 + c] - anchors[aidx*4 + c];
        float d = fabsf(pred - tgt);
        bsum = (d < 1.f) ? 0.5f*d*d : d - 0.5f;
    }
    float rpnReg = blockReduceSum512(bsum, sbuf) / 512.f / 4.f;

    float csum = 0.f, accsum = 0.f;
    if (tid < 256) {
        int j = tid;
        int cls = 0;
        if (j < NPOS_) {
            int i = g_posr[j];
            int b = i / R_;
            cls = classes[b*T_ + g_ridx[i]];
        }
        const float* row = &g_rcls[j*NCLS_];
        float mx = row[0];
        #pragma unroll
        for (int c = 1; c < NCLS_; c++) mx = fmaxf(mx, row[c]);
        float se = 0.f;
        #pragma unroll
        for (int c = 0; c < NCLS_; c++) se += expf(row[c] - mx);
        float lse = mx + logf(se);
        csum = lse - row[cls];
        if (j < NPOS_) {
            int am = 0; float bv = row[0];
            #pragma unroll
            for (int c = 1; c < NCLS_; c++) if (row[c] > bv) { bv = row[c]; am = c; }
            accsum = (am == cls) ? 1.f : 0.f;
        }
    }
    float rcnnCls = blockReduceSum512(csum, sbuf) / 256.f;
    float acc     = blockReduceSum512(accsum, sbuf) / (float)NPOS_;

    float dsl = 0.f, dab = 0.f;
    if (tid < NPOS_*4) {
        int jj = tid >> 2, c = tid & 3;
        int i = g_posr[jj];
        int b = i / R_;
        float v = nms_reg[i*4 + c];
        float rounded = (c < 2) ? floorf(v * 16.f) / 16.f : ceilf(v * 16.f) / 16.f;
        float mb = bboxes[(b*T_ + g_ridx[i])*4 + c];
        float tgt = mb - rounded;
        float pr = g_rreg[jj*4 + c];
        float d = fabsf(pr - tgt);
        dsl = (d < 1.f) ? 0.5f*d*d : d - 0.5f;
        dab = d;
    }
    float rcnnReg = blockReduceSum512(dsl, sbuf) / (float)NPOS_ / 4.f;
    float offset  = blockReduceSum512(dab, sbuf) / (float)NPOS_ / 4.f;

    if (tid == 0) {
        out[0] = rpnCls;
        out[1] = rpnReg;
        out[2] = rcnnCls;
        out[3] = rcnnReg;
        out[4] = acc;
        out[5] = offset;
    }
}

// ---------------- launch ----------------
extern "C" void kernel_launch(void* const* d_in, const int* in_sizes, int n_in,
                              void* d_out, int out_size) {
    const float* nms_reg  = (const float*)d_in[0];
    const float* fm       = (const float*)d_in[2];
    const float* bboxes   = (const float*)d_in[3];
    const int*   classes  = (const int*)  d_in[4];
    const float* anchors  = (const float*)d_in[5];
    const float* rpn_reg  = (const float*)d_in[6];
    const float* rpn_cls  = (const float*)d_in[7];
    const float* W1       = (const float*)d_in[8];
    const float* b1       = (const float*)d_in[9];
    const float* Wr       = (const float*)d_in[10];
    const float* br       = (const float*)d_in[11];
    const float* Wc       = (const float*)d_in[12];
    const float* bc       = (const float*)d_in[13];
    float* out = (float*)d_out;

    cudaFuncSetAttribute(gemm_mma_kernel, cudaFuncAttributeMaxDynamicSharedMemorySize, SMEM_GEMM_);

    prep_kernel<<<PB_TOTAL, 256>>>(fm, bboxes, anchors, nms_reg);
    rpn_count_kernel<<<18, 1024>>>();
    rpn_place_kernel<<<18, 1024>>>();
    topk_posr_kernel<<<1, 1024>>>();
    roi_pool_kernel<<<256, 256>>>(nms_reg);
    gemm_mma_kernel<<<dim3(16, 2, KT_), 256, SMEM_GEMM_>>>(W1);
    reduce_bias_relu_kernel<<<256, 256>>>(b1);
    heads_kernel<<<256, 128>>>(Wr, br, Wc, bc);
    finalize_kernel<<<1, 512>>>(nms_reg, bboxes, classes, anchors, rpn_reg, rpn_cls, out);
}

// round 6
// speedup vs baseline: 3.6142x; 1.1300x over previous
#include <cuda_runtime.h>
#include <cuda_bf16.h>
#include <math.h>
#include <stdint.h>

#define B_ 4
#define T_ 40
#define R_ 2000
#define A_ 36864
#define H_ 64
#define W_ 64
#define C_ 256
#define PP_ 7
#define NCLS_ 21
#define NPOS_ 64
#define NNEG_ 192
#define DH_ 1024
#define D_ (PP_*PP_*C_)   // 12544
#define KT_ 8             // split-K factor
#define KPC_ (D_/KT_)     // 1568 per CTA
#define BK_ 32
#define NIT_ (KPC_/BK_)   // 49

// GEMM smem: A tiles bf16 rows padded to 40 elems (80B); B tile fp32 rows padded to 68 words
#define TPAD_ 40
#define ATILE_ (128*TPAD_*2)            // 10240
#define BPADW_ 68
#define BTILEF_ (32*BPADW_*4)           // 8704
#define STAGE_ (2*ATILE_ + BTILEF_)     // 29184
#define NSTG_ 3
#define SMEM_GEMM_ (NSTG_*STAGE_)       // 87552

// ---------------- scratch ----------------
__device__ float g_fmt[B_*H_*W_*C_];
__device__ float g_maxiou[B_*A_];
__device__ int   g_tidx[B_*A_];
__device__ float g_ioum[B_*R_];
__device__ int   g_ridx[B_*R_];
__device__ int   g_pos[128];
__device__ int   g_neg[252];
__device__ int   g_posr[NPOS_];
__device__ int   g_negr[NNEG_];
__device__ int   g_cntP[18], g_cntN[18];
__device__ int   g_cntReady;
__device__ int   g_selDone;
__device__ __nv_bfloat16 g_Ahi[256*D_];
__device__ __nv_bfloat16 g_Alo[256*D_];
__device__ float g_partial[KT_][256*DH_];
__device__ float g_rreg[256*4];
__device__ float g_rcls[256*NCLS_];

__device__ __forceinline__ uint32_t smem_u32(const void* p) {
    uint32_t a;
    asm("{ .reg .u64 t; cvta.to.shared.u64 t, %1; cvt.u32.u64 %0, t; }" : "=r"(a) : "l"(p));
    return a;
}
__device__ __forceinline__ unsigned fkey(float f) {
    unsigned u = __float_as_uint(f);
    return (u & 0x80000000u) ? ~u : (u | 0x80000000u);
}

// ---------------- fused prep: init | transpose | rpn_iou | rcnn_iou ----------------
#define PB_TRANS 4096                   // 2*8*256
#define PB_RPN   576                    // 144*4
#define PB_RCNN  32                     // 8*4
#define PB_TOTAL (PB_TRANS + PB_RPN + PB_RCNN + 1)

__global__ void prep_kernel(const float* __restrict__ fm,
                            const float* __restrict__ bboxes,
                            const float* __restrict__ anchors,
                            const float* __restrict__ nms_reg) {
    __shared__ float tile[32][33];
    int blk = blockIdx.x;
    int tid = threadIdx.x;          // 256
    if (blk < PB_TRANS) {
        int bh = blk >> 4;
        int sub = blk & 15;
        int x0 = (sub & 1) * 32, c0 = (sub >> 1) * 32;
        int b = bh >> 6, y = bh & 63;
        int tx = tid & 31, ty = tid >> 5;
        #pragma unroll
        for (int i = 0; i < 4; i++) {
            int c = c0 + ty + i*8;
            tile[ty + i*8][tx] = fm[((b*C_ + c)*H_ + y)*W_ + x0 + tx];
        }
        __syncthreads();
        #pragma unroll
        for (int i = 0; i < 4; i++) {
            int xr = ty + i*8;
            g_fmt[((b*H_ + y)*W_ + x0+xr)*C_ + c0+tx] = tile[tx][xr];
        }
        return;
    }
    blk -= PB_TRANS;
    if (blk < PB_RPN) {
        int b = blk / 144, bx = blk % 144;
        float* sb = &tile[0][0];
        if (tid < T_*4) sb[tid] = bboxes[b*T_*4 + tid];
        __syncthreads();
        int a = bx*256 + tid;
        float4 an = ((const float4*)anchors)[a];
        float area2 = (an.z-an.x)*(an.w-an.y);
        float best = -1.0f; int bi = 0;
        #pragma unroll 4
        for (int t = 0; t < T_; t++) {
            float bt = sb[t*4+0], bl = sb[t*4+1], bb = sb[t*4+2], br = sb[t*4+3];
            float inter = fmaxf(fminf(bb,an.z)-fmaxf(bt,an.x),0.f)
                        * fmaxf(fminf(br,an.w)-fmaxf(bl,an.y),0.f);
            float a1 = (bb-bt)*(br-bl);
            float iou = inter / (a1 + area2 - inter);
            if (iou > best) { best = iou; bi = t; }
        }
        g_maxiou[b*A_+a] = best;
        g_tidx[b*A_+a] = bi;
        return;
    }
    blk -= PB_RPN;
    if (blk < PB_RCNN) {
        int b = blk >> 3, rx = blk & 7;
        float* sb = &tile[0][0];
        if (tid < T_*4) sb[tid] = bboxes[b*T_*4 + tid];
        __syncthreads();
        int r = rx*256 + tid;
        if (r >= R_) return;
        float4 nr4 = ((const float4*)nms_reg)[b*R_+r];
        float area1 = (nr4.z-nr4.x)*(nr4.w-nr4.y);
        float best = -1.0f; int bi = 0;
        #pragma unroll 4
        for (int t = 0; t < T_; t++) {
            float bt = sb[t*4+0], bl = sb[t*4+1], bb = sb[t*4+2], br = sb[t*4+3];
            float inter = fmaxf(fminf(bb,nr4.z)-fmaxf(bt,nr4.x),0.f)
                        * fmaxf(fminf(br,nr4.w)-fmaxf(bl,nr4.y),0.f);
            float a2 = (bb-bt)*(br-bl);
            float iou = inter / (area1 + a2 - inter);
            if (iou > best) { best = iou; bi = t; }
        }
        g_ioum[b*R_+r] = best;
        g_ridx[b*R_+r] = bi;
        return;
    }
    // init block
    if (tid < 128)  g_pos[tid]  = 0;
    if (tid < 252)  g_neg[tid]  = 0;
    if (tid < NPOS_) g_posr[tid] = 0;
    if (tid == 0) { g_cntReady = 0; g_selDone = 0; }
}

// ============ fused selection: rpn(blocks 0-17) | topk+posr(18) | roi(19-82) ============
#define SEL_RPN_ 18
#define SEL_TOPK_ 18
#define SEL_ROI0_ 19
#define SEL_NBLK_ 83

__global__ void __launch_bounds__(1024, 2) sel_kernel(const float* __restrict__ nms_reg) {
    __shared__ float sv[B_*R_];           // topk values (also unused by other roles)
    __shared__ int hist[256];
    __shared__ int sS[256];
    __shared__ int sCnt[32], sOff[32], sCnt2[32], sOff2[32];
    __shared__ int sTot, sTot2;
    __shared__ unsigned sPrefix;
    __shared__ int sRemain, sCntG;
    __shared__ int sBaseP, sBaseN;

    int blk = blockIdx.x;
    int tid = threadIdx.x, lane = tid & 31, wid = tid >> 5;

    if (blk < SEL_RPN_) {
        // ---- RPN chunk: count, publish, wait, place ----
        int c = blk;
        int cp = 0;
        float v8[8];
        #pragma unroll
        for (int i = 0; i < 8; i++) {
            v8[i] = g_maxiou[c*8192 + i*1024 + tid];
            cp += (v8[i] > 0.5f) ? 1 : 0;
        }
        #pragma unroll
        for (int d = 16; d; d >>= 1) cp += __shfl_down_sync(0xffffffffu, cp, d);
        if (lane == 0) sCnt[wid] = cp;
        __syncthreads();
        if (wid == 0) {
            int s = sCnt[lane];
            #pragma unroll
            for (int d = 16; d; d >>= 1) s += __shfl_down_sync(0xffffffffu, s, d);
            if (lane == 0) {
                g_cntP[c] = s; g_cntN[c] = 8192 - s;
                __threadfence();
                atomicAdd(&g_cntReady, 1);
            }
        }
        if (tid == 0) {
            while (atomicAdd(&g_cntReady, 0) < 18) {}
            int bp = 0, bn = 0;
            for (int i = 0; i < c; i++) { bp += g_cntP[i]; bn += g_cntN[i]; }
            sBaseP = bp; sBaseN = bn;
        }
        __syncthreads();
        int baseP = sBaseP, baseN = sBaseN;
        if (baseP >= 128 && baseN >= 252) return;
        for (int ph = 0; ph < 8; ph++) {
            int j = c*8192 + ph*1024 + tid;
            bool fp = (v8[ph] > 0.5f), fn = !fp;
            unsigned mp = __ballot_sync(0xffffffffu, fp);
            unsigned mn = __ballot_sync(0xffffffffu, fn);
            if (lane == 0) { sCnt[wid] = __popc(mp); sCnt2[wid] = __popc(mn); }
            __syncthreads();
            if (wid == 0) {
                int cp2 = sCnt[lane], cn2 = sCnt2[lane];
                int sp = cp2, sn = cn2;
                #pragma unroll
                for (int d = 1; d < 32; d <<= 1) {
                    int tp = __shfl_up_sync(0xffffffffu, sp, d);
                    int tn = __shfl_up_sync(0xffffffffu, sn, d);
                    if (lane >= d) { sp += tp; sn += tn; }
                }
                sOff[lane] = sp - cp2; sOff2[lane] = sn - cn2;
                if (lane == 31) { sTot = sp; sTot2 = sn; }
            }
            __syncthreads();
            if (fp) {
                int p = baseP + sOff[wid] + __popc(mp & ((1u << lane) - 1u));
                if (p < 128) g_pos[p] = j;
            }
            if (fn) {
                int p = baseN + sOff2[wid] + __popc(mn & ((1u << lane) - 1u));
                if (p < 252) g_neg[p] = j;
            }
            baseP += sTot; baseN += sTot2;
            __syncthreads();
            if (baseP >= 128 && baseN >= 252) return;
        }
        return;
    }

    if (blk == SEL_TOPK_) {
        // ---- topk(192) radix-select + posr first-64 ----
        for (int j = tid; j < B_*R_; j += 1024) {
            float v = g_ioum[j];
            sv[j] = (v <= 0.5f) ? v : -INFINITY;
        }
        if (tid == 0) { sPrefix = 0; sRemain = NNEG_; sCntG = 0; }
        __syncthreads();

        // posr: first 64 with iou > 0.5, index order
        int base = 0;
        for (int ph = 0; ph < 8 && base < NPOS_; ph++) {
            int j = ph*1024 + tid;
            bool f = (j < B_*R_) && (g_ioum[j] > 0.5f);
            unsigned m = __ballot_sync(0xffffffffu, f);
            if (lane == 0) sCnt[wid] = __popc(m);
            __syncthreads();
            if (wid == 0) {
                int cp = sCnt[lane], sp = cp;
                #pragma unroll
                for (int d = 1; d < 32; d <<= 1) {
                    int tp = __shfl_up_sync(0xffffffffu, sp, d);
                    if (lane >= d) sp += tp;
                }
                sOff[lane] = sp - cp;
                if (lane == 31) sTot = sp;
            }
            __syncthreads();
            if (f) {
                int p = base + sOff[wid] + __popc(m & ((1u << lane) - 1u));
                if (p < NPOS_) g_posr[p] = j;
            }
            base += sTot;
            __syncthreads();
        }

        // radix select threshold key (top-192, ties -> lowest index)
        for (int lvl = 24; lvl >= 0; lvl -= 8) {
            if (tid < 256) hist[tid] = 0;
            __syncthreads();
            unsigned pfx = sPrefix;
            int need = sRemain;
            for (int j = tid; j < B_*R_; j += 1024) {
                unsigned k = fkey(sv[j]);
                bool match = (lvl == 24) || ((k >> (lvl+8)) == pfx);
                if (match) atomicAdd(&hist[(k >> lvl) & 255], 1);
            }
            __syncthreads();
            // parallel suffix sum over 256 bins
            if (tid < 256) sS[tid] = hist[tid];
            __syncthreads();
            #pragma unroll
            for (int d = 1; d < 256; d <<= 1) {
                int v = 0;
                if (tid < 256 && tid + d < 256) v = sS[tid + d];
                __syncthreads();
                if (tid < 256) sS[tid] += v;
                __syncthreads();
            }
            if (tid < 256) {
                int Sb = sS[tid];
                int Snext = (tid < 255) ? sS[tid+1] : 0;
                if (Sb >= need && Snext < need) {      // unique winner (S monotone)
                    sPrefix = (pfx << 8) | (unsigned)tid;
                    sRemain = need - Snext;
                }
            }
            __syncthreads();
        }
        unsigned K = sPrefix;
        int needEq = sRemain;
        int G = NNEG_ - needEq;

        // strictly greater: set-only, atomic append
        for (int j = tid; j < B_*R_; j += 1024) {
            if (fkey(sv[j]) > K) {
                int p = atomicAdd(&sCntG, 1);
                g_negr[p] = j;
            }
        }
        __syncthreads();
        // equals: lowest needEq indices, ordered
        base = 0;
        for (int ph = 0; ph < 8 && base < needEq; ph++) {
            int j = ph*1024 + tid;
            bool f = (j < B_*R_) && (fkey(sv[j]) == K);
            unsigned m = __ballot_sync(0xffffffffu, f);
            if (lane == 0) sCnt[wid] = __popc(m);
            __syncthreads();
            if (wid == 0) {
                int cp = sCnt[lane], sp = cp;
                #pragma unroll
                for (int d = 1; d < 32; d <<= 1) {
                    int tp = __shfl_up_sync(0xffffffffu, sp, d);
                    if (lane >= d) sp += tp;
                }
                sOff[lane] = sp - cp;
                if (lane == 31) sTot = sp;
            }
            __syncthreads();
            if (f) {
                int p = base + sOff[wid] + __popc(m & ((1u << lane) - 1u));
                if (p < needEq) g_negr[G + p] = j;
            }
            base += sTot;
            __syncthreads();
        }
        __syncthreads();
        if (tid == 0) {
            __threadfence();
            atomicExch(&g_selDone, 1);
        }
        return;
    }

    // ---- ROI pool: 4 rois per block, spin on topk done ----
    if (tid == 0) {
        while (atomicAdd(&g_selDone, 0) == 0) {}
    }
    __syncthreads();
    int j = (blk - SEL_ROI0_) * 4 + (tid >> 8);
    int c = tid & 255;
    int sel = (j < NPOS_) ? g_posr[j] : g_negr[j - NPOS_];
    int b = sel / R_;
    float t  = nms_reg[sel*4+0], l = nms_reg[sel*4+1];
    float bb = nms_reg[sel*4+2], r = nms_reg[sel*4+3];
    const float* fb = g_fmt + (size_t)b * H_ * W_ * C_;
    for (int p = 0; p < PP_*PP_; p++) {
        int py = p / PP_, px = p % PP_;
        float gy = (py + 0.5f) / (float)PP_;
        float gx = (px + 0.5f) / (float)PP_;
        float y = fminf(fmaxf(t + gy * (bb - t), 0.f), (float)(H_-1));
        float x = fminf(fmaxf(l + gx * (r  - l), 0.f), (float)(W_-1));
        int y0 = (int)floorf(y), x0 = (int)floorf(x);
        int y1 = min(y0 + 1, H_-1), x1 = min(x0 + 1, W_-1);
        float wy = y - (float)y0, wx = x - (float)x0;
        float v00 = fb[(y0*W_+x0)*C_ + c];
        float v01 = fb[(y0*W_+x1)*C_ + c];
        float v10 = fb[(y1*W_+x0)*C_ + c];
        float v11 = fb[(y1*W_+x1)*C_ + c];
        float v = v00*(1.f-wy)*(1.f-wx) + v01*(1.f-wy)*wx
                + v10*wy*(1.f-wx)       + v11*wy*wx;
        __nv_bfloat16 h = __float2bfloat16(v);
        int o = j*D_ + p*C_ + c;
        g_Ahi[o] = h;
        g_Alo[o] = __float2bfloat16(v - __bfloat162float(h));
    }
}

// ---------------- mma.sync GEMM: BM128 BN64 BK32, 3-stage, split-K=8 ----------------
__device__ __forceinline__ void ldsm_x4(uint32_t* r, uint32_t addr) {
    asm volatile("ldmatrix.sync.aligned.m8n8.x4.shared.b16 {%0,%1,%2,%3}, [%4];"
        : "=r"(r[0]), "=r"(r[1]), "=r"(r[2]), "=r"(r[3]) : "r"(addr));
}
__device__ __forceinline__ void mma16816(float* d, const uint32_t* a, const uint32_t* b) {
    asm volatile("mma.sync.aligned.m16n8k16.row.col.f32.bf16.bf16.f32 "
        "{%0,%1,%2,%3}, {%4,%5,%6,%7}, {%8,%9}, {%0,%1,%2,%3};"
        : "+f"(d[0]), "+f"(d[1]), "+f"(d[2]), "+f"(d[3])
        : "r"(a[0]), "r"(a[1]), "r"(a[2]), "r"(a[3]), "r"(b[0]), "r"(b[1]));
}
__device__ __forceinline__ void cp16(uint32_t saddr, const void* gaddr) {
    asm volatile("cp.async.cg.shared.global [%0], [%1], 16;" :: "r"(saddr), "l"(gaddr));
}

__global__ void __launch_bounds__(256, 2) gemm_mma_kernel(const float* __restrict__ W1) {
    extern __shared__ char smem[];
    uint32_t sb = smem_u32(smem);
    int tid = threadIdx.x, wid = tid >> 5, lane = tid & 31;
    int n0 = blockIdx.x * 64;
    int m0 = blockIdx.y * 128;
    int kt = blockIdx.z;
    int kbase = kt * KPC_;
    int wm = wid >> 1, wn = wid & 1;     // warp tile 32x32

    const uint4* bAhi = (const uint4*)g_Ahi + (size_t)m0 * (D_/8);
    const uint4* bAlo = (const uint4*)g_Alo + (size_t)m0 * (D_/8);

    int a0r = tid >> 2,          a0q = tid & 3;
    int a1r = (tid + 256) >> 2,  a1q = tid & 3;
    int b0r = tid >> 4, b0q = tid & 15;

    auto load_stage = [&](int it) {
        uint32_t sg = sb + (it % NSTG_) * STAGE_;
        int kk = kbase + it*BK_;
        int kq = kk >> 3;
        cp16(sg +          a0r*80 + a0q*16, bAhi + (size_t)a0r*(D_/8) + kq + a0q);
        cp16(sg +          a1r*80 + a1q*16, bAhi + (size_t)a1r*(D_/8) + kq + a1q);
        cp16(sg + ATILE_ + a0r*80 + a0q*16, bAlo + (size_t)a0r*(D_/8) + kq + a0q);
        cp16(sg + ATILE_ + a1r*80 + a1q*16, bAlo + (size_t)a1r*(D_/8) + kq + a1q);
        uint32_t bg = sg + 2*ATILE_;
        cp16(bg + b0r*(BPADW_*4) + b0q*16,      W1 + (size_t)(kk + b0r)*DH_ + n0 + b0q*4);
        cp16(bg + (b0r+16)*(BPADW_*4) + b0q*16, W1 + (size_t)(kk + b0r+16)*DH_ + n0 + b0q*4);
        asm volatile("cp.async.commit_group;");
    };

    float acc[2][4][4];
    #pragma unroll
    for (int i = 0; i < 2; i++)
        #pragma unroll
        for (int j = 0; j < 4; j++)
            #pragma unroll
            for (int q = 0; q < 4; q++) acc[i][j][q] = 0.f;

    load_stage(0);
    load_stage(1);

    for (int it = 0; it < NIT_; it++) {
        asm volatile("cp.async.wait_group 1;");
        __syncthreads();
        if (it + 2 < NIT_) load_stage(it + 2);
        else asm volatile("cp.async.commit_group;");

        uint32_t sg = sb + (it % NSTG_) * STAGE_;
        uint32_t aHiB = sg, aLoB = sg + ATILE_;
        const float* sBf = (const float*)(smem + (it % NSTG_) * STAGE_ + 2*ATILE_);

        #pragma unroll
        for (int ks = 0; ks < 2; ks++) {
            int acol = ks*16 + ((lane >> 4) & 1) * 8;
            uint32_t ahi[2][4], alo[2][4], bhi[4][2], blo[4][2];
            #pragma unroll
            for (int mt = 0; mt < 2; mt++) {
                int arow = wm*32 + mt*16 + (lane & 15);
                uint32_t off = arow*80 + acol*2;
                ldsm_x4(ahi[mt], aHiB + off);
                ldsm_x4(alo[mt], aLoB + off);
            }
            #pragma unroll
            for (int nt = 0; nt < 4; nt++) {
                int nn = wn*32 + nt*8 + (lane >> 2);
                #pragma unroll
                for (int rg = 0; rg < 2; rg++) {
                    int kk2 = ks*16 + (lane & 3)*2 + rg*8;
                    float v0 = sBf[(kk2+0)*BPADW_ + nn];
                    float v1 = sBf[(kk2+1)*BPADW_ + nn];
                    uint32_t hreg;
                    asm("cvt.rn.bf16x2.f32 %0, %1, %2;" : "=r"(hreg) : "f"(v1), "f"(v0));
                    float h0 = __uint_as_float(hreg << 16);
                    float h1 = __uint_as_float(hreg & 0xFFFF0000u);
                    uint32_t lreg;
                    asm("cvt.rn.bf16x2.f32 %0, %1, %2;" : "=r"(lreg) : "f"(v1-h1), "f"(v0-h0));
                    bhi[nt][rg] = hreg;
                    blo[nt][rg] = lreg;
                }
            }
            #pragma unroll
            for (int mt = 0; mt < 2; mt++)
                #pragma unroll
                for (int nt = 0; nt < 4; nt++) {
                    mma16816(acc[mt][nt], ahi[mt], bhi[nt]);
                    mma16816(acc[mt][nt], ahi[mt], blo[nt]);
                    mma16816(acc[mt][nt], alo[mt], bhi[nt]);
                }
        }
    }

    float* outp = g_partial[kt];
    int g = lane >> 2, qc = (lane & 3) * 2;
    #pragma unroll
    for (int mt = 0; mt < 2; mt++) {
        #pragma unroll
        for (int nt = 0; nt < 4; nt++) {
            int row = m0 + wm*32 + mt*16 + g;
            int col = n0 + wn*32 + nt*8 + qc;
            *(float2*)&outp[(size_t)row*DH_ + col]     = make_float2(acc[mt][nt][0], acc[mt][nt][1]);
            *(float2*)&outp[(size_t)(row+8)*DH_ + col] = make_float2(acc[mt][nt][2], acc[mt][nt][3]);
        }
    }
}

// ---------------- fused: reduce partials + bias + relu + heads ----------------
__global__ void mlp_tail_kernel(const float* __restrict__ b1,
                                const float* __restrict__ Wr, const float* __restrict__ br,
                                const float* __restrict__ Wc, const float* __restrict__ bc) {
    __shared__ float h[DH_];
    int row = blockIdx.x;
    int tid = threadIdx.x;              // 256
    const float4* b4 = (const float4*)b1;
    float4 s = b4[tid];
    #pragma unroll
    for (int k = 0; k < KT_; k++) {
        float4 p = ((const float4*)(g_partial[k] + (size_t)row*DH_))[tid];
        s.x += p.x; s.y += p.y; s.z += p.z; s.w += p.w;
    }
    h[tid*4+0] = fmaxf(s.x, 0.f);
    h[tid*4+1] = fmaxf(s.y, 0.f);
    h[tid*4+2] = fmaxf(s.z, 0.f);
    h[tid*4+3] = fmaxf(s.w, 0.f);
    __syncthreads();
    int wid = tid >> 5, lane = tid & 31;
    for (int o = wid; o < 4 + NCLS_; o += 8) {
        float sum = 0.f;
        if (o < 4) {
            for (int k = lane; k < DH_; k += 32) sum += h[k] * Wr[k*4 + o];
        } else {
            int oc = o - 4;
            for (int k = lane; k < DH_; k += 32) sum += h[k] * Wc[k*NCLS_ + oc];
        }
        #pragma unroll
        for (int d = 16; d; d >>= 1) sum += __shfl_down_sync(0xffffffffu, sum, d);
        if (lane == 0) {
            if (o < 4) g_rreg[row*4 + o] = sum + br[o];
            else       g_rcls[row*NCLS_ + (o-4)] = sum + bc[o-4];
        }
    }
}

// ---------------- finalize ----------------
__device__ float blockReduceSum512(float v, float* sbuf) {
    int tid = threadIdx.x;
    sbuf[tid] = v; __syncthreads();
    for (int s = 256; s > 0; s >>= 1) {
        if (tid < s) sbuf[tid] += sbuf[tid + s];
        __syncthreads();
    }
    float r = sbuf[0]; __syncthreads();
    return r;
}

__global__ void finalize_kernel(const float* __restrict__ nms_reg,
                                const float* __restrict__ bboxes,
                                const int*   __restrict__ classes,
                                const float* __restrict__ anchors,
                                const float* __restrict__ rpn_reg,
                                const float* __restrict__ rpn_cls,
                                float* __restrict__ out) {
    __shared__ float sbuf[512];
    int tid = threadIdx.x;

    float a = 0.f;
    if (tid < 380) {
        int i = (tid < 128) ? g_pos[tid] : g_neg[tid - 128];
        float x = rpn_cls[i];
        float lbl = (tid < 128) ? 1.f : 0.f;
        a = fmaxf(x, 0.f) - x * lbl + log1pf(expf(-fabsf(x)));
    }
    float rpnCls = blockReduceSum512(a, sbuf) / 380.f;

    float bsum = 0.f;
    {
        int jj = tid >> 2, c = tid & 3;
        int i = g_pos[jj];
        int b = i / A_;
        int aidx = i - b * A_;
        float pred = rpn_reg[i*4 + c];
        float tgt = bboxes[(b*T_ + g_tidx[i])*4 + c] - anchors[aidx*4 + c];
        float d = fabsf(pred - tgt);
        bsum = (d < 1.f) ? 0.5f*d*d : d - 0.5f;
    }
    float rpnReg = blockReduceSum512(bsum, sbuf) / 512.f / 4.f;

    float csum = 0.f, accsum = 0.f;
    if (tid < 256) {
        int j = tid;
        int cls = 0;
        if (j < NPOS_) {
            int i = g_posr[j];
            int b = i / R_;
            cls = classes[b*T_ + g_ridx[i]];
        }
        const float* row = &g_rcls[j*NCLS_];
        float mx = row[0];
        #pragma unroll
        for (int c = 1; c < NCLS_; c++) mx = fmaxf(mx, row[c]);
        float se = 0.f;
        #pragma unroll
        for (int c = 0; c < NCLS_; c++) se += expf(row[c] - mx);
        float lse = mx + logf(se);
        csum = lse - row[cls];
        if (j < NPOS_) {
            int am = 0; float bv = row[0];
            #pragma unroll
            for (int c = 1; c < NCLS_; c++) if (row[c] > bv) { bv = row[c]; am = c; }
            accsum = (am == cls) ? 1.f : 0.f;
        }
    }
    float rcnnCls = blockReduceSum512(csum, sbuf) / 256.f;
    float acc     = blockReduceSum512(accsum, sbuf) / (float)NPOS_;

    float dsl = 0.f, dab = 0.f;
    if (tid < NPOS_*4) {
        int jj = tid >> 2, c = tid & 3;
        int i = g_posr[jj];
        int b = i / R_;
        float v = nms_reg[i*4 + c];
        float rounded = (c < 2) ? floorf(v * 16.f) / 16.f : ceilf(v * 16.f) / 16.f;
        float mb = bboxes[(b*T_ + g_ridx[i])*4 + c];
        float tgt = mb - rounded;
        float pr = g_rreg[jj*4 + c];
        float d = fabsf(pr - tgt);
        dsl = (d < 1.f) ? 0.5f*d*d : d - 0.5f;
        dab = d;
    }
    float rcnnReg = blockReduceSum512(dsl, sbuf) / (float)NPOS_ / 4.f;
    float offset  = blockReduceSum512(dab, sbuf) / (float)NPOS_ / 4.f;

    if (tid == 0) {
        out[0] = rpnCls;
        out[1] = rpnReg;
        out[2] = rcnnCls;
        out[3] = rcnnReg;
        out[4] = acc;
        out[5] = offset;
    }
}

// ---------------- launch ----------------
extern "C" void kernel_launch(void* const* d_in, const int* in_sizes, int n_in,
                              void* d_out, int out_size) {
    const float* nms_reg  = (const float*)d_in[0];
    const float* fm       = (const float*)d_in[2];
    const float* bboxes   = (const float*)d_in[3];
    const int*   classes  = (const int*)  d_in[4];
    const float* anchors  = (const float*)d_in[5];
    const float* rpn_reg  = (const float*)d_in[6];
    const float* rpn_cls  = (const float*)d_in[7];
    const float* W1       = (const float*)d_in[8];
    const float* b1       = (const float*)d_in[9];
    const float* Wr       = (const float*)d_in[10];
    const float* br       = (const float*)d_in[11];
    const float* Wc       = (const float*)d_in[12];
    const float* bc       = (const float*)d_in[13];
    float* out = (float*)d_out;

    cudaFuncSetAttribute(gemm_mma_kernel, cudaFuncAttributeMaxDynamicSharedMemorySize, SMEM_GEMM_);

    prep_kernel<<<PB_TOTAL, 256>>>(fm, bboxes, anchors, nms_reg);
    sel_kernel<<<SEL_NBLK_, 1024>>>(nms_reg);
    gemm_mma_kernel<<<dim3(16, 2, KT_), 256, SMEM_GEMM_>>>(W1);
    mlp_tail_kernel<<<256, 256>>>(b1, Wr, br, Wc, bc);
    finalize_kernel<<<1, 512>>>(nms_reg, bboxes, classes, anchors, rpn_reg, rpn_cls, out);
}